// round 11
// baseline (speedup 1.0000x reference)
#include <cuda_runtime.h>
#include <cuda_fp16.h>

// ---------------------------------------------------------------------------
// 3-layer GCN persistent megakernel, round 11:
//  - warp-cooperative gathers: 1 warp per node, lanes = edge-slot x chunk
//    (4x8 for layer1, 8x4 for layer2), shfl cross-slot reduction
//  - CSR padded to 8 entries (pads = self; coef corrects exactly)
//  - fp16 feature storage, fp32 accumulation (round-9 scheme)
//  - fp32 GEMMs w/ dynamic 64-row tiles (FMA-issue floor, left alone)
// ---------------------------------------------------------------------------

#define NMAX 100000
#define EMAX 1600000
#define CSRMAX (EMAX + 8 * NMAX)
#define NB  740          // 148 SMs x 5 CTAs
#define TPB 256
#define NTH (NB * TPB)
#define NWARPS (NTH >> 5)

__device__ unsigned g_bar;        // zero-init; restored to 0 at exit
__device__ int   g_alloc;         // restored at exit
__device__ int   g_work[8];       // GEMM tile counters; restored at exit
__device__ int   g_deg[NMAX];     // zeroed by previous run's final phase
__device__ int   g_rowptr[NMAX];
__device__ int   g_cursor[NMAX];  // zeroed by previous run's gather1 phase
__device__ float g_dis[NMAX];
__device__ __align__(16) int g_csr[CSRMAX];     // src indices; pads = dst itself
__device__ __align__(16) __half g_h16[(size_t)NMAX * 64];  // fp16 features
__device__ float g_o[(size_t)NMAX * 64];

struct SM {
    __align__(16) float w[4096];
    int tile;
    int is64;
};

__device__ __forceinline__ float fast_tanh(float x) {
    float y;
    asm("tanh.approx.f32 %0, %1;" : "=f"(y) : "f"(x));
    return y;
}

__device__ __forceinline__ void gsync(unsigned target) {
    __syncthreads();
    if (threadIdx.x == 0) {
        __threadfence();
        atomicAdd(&g_bar, 1u);
        while (*((volatile unsigned*)&g_bar) < target) __nanosleep(64);
    }
    __syncthreads();
}

__device__ __forceinline__ int edge_at(const void* ei, size_t idx, int is64) {
    if (is64) return (int)((const long long*)ei)[idx];
    return ((const int*)ei)[idx];
}

__device__ __forceinline__ void h8_acc(float* acc, uint4 q) {
    float2 t;
    t = __half22float2(*(__half2*)&q.x); acc[0] += t.x; acc[1] += t.y;
    t = __half22float2(*(__half2*)&q.y); acc[2] += t.x; acc[3] += t.y;
    t = __half22float2(*(__half2*)&q.z); acc[4] += t.x; acc[5] += t.y;
    t = __half22float2(*(__half2*)&q.w); acc[6] += t.x; acc[7] += t.y;
}
__device__ __forceinline__ void h8_unpack(uint4 q, float* f) {
    float2 t;
    t = __half22float2(*(__half2*)&q.x); f[0] = t.x; f[1] = t.y;
    t = __half22float2(*(__half2*)&q.y); f[2] = t.x; f[3] = t.y;
    t = __half22float2(*(__half2*)&q.z); f[4] = t.x; f[5] = t.y;
    t = __half22float2(*(__half2*)&q.w); f[6] = t.x; f[7] = t.y;
}

// ---- GEMM: O16[N,M] = fp16( dis[row] * (X[N,K] @ W[K,M]) ), dyn 64-row tiles
template <int K, int M>
__device__ void gemm_phase(const float* __restrict__ X, const float* __restrict__ W,
                           __half* __restrict__ O16, int N, SM* sm, int workid) {
    constexpr int TN = M / 16;
    for (int i = threadIdx.x; i < K * M; i += TPB) sm->w[i] = W[i];
    int cg = threadIdx.x & 15;
    int rg = threadIdx.x >> 4;
    int tiles = (N + 63) >> 6;
    const float4* __restrict__ X4 = (const float4*)X;
    for (;;) {
        __syncthreads();
        if (threadIdx.x == 0) sm->tile = atomicAdd(&g_work[workid], 1);
        __syncthreads();
        int tile = sm->tile;
        if (tile >= tiles) break;
        int row0 = tile * 64 + rg * 4;
        bool full = (row0 + 3 < N);
        float acc[4][TN];
        #pragma unroll
        for (int r = 0; r < 4; r++)
            #pragma unroll
            for (int t = 0; t < TN; t++) acc[r][t] = 0.f;
        #pragma unroll 2
        for (int k4 = 0; k4 < K / 4; k4++) {
            float4 xv[4];
            #pragma unroll
            for (int r = 0; r < 4; r++) {
                int row = row0 + r;
                if (full || row < N) xv[r] = __ldg(&X4[(size_t)row * (K / 4) + k4]);
                else xv[r] = make_float4(0.f, 0.f, 0.f, 0.f);
            }
            #pragma unroll
            for (int kk = 0; kk < 4; kk++) {
                int k = k4 * 4 + kk;
                float wv[TN];
                if (TN == 4) {
                    float4 wq = ((const float4*)sm->w)[k * (M / 4) + cg];
                    wv[0] = wq.x; wv[1] = wq.y; wv[2] = wq.z; wv[3] = wq.w;
                } else {
                    float2 wq = ((const float2*)sm->w)[k * (M / 2) + cg];
                    wv[0] = wq.x; wv[1] = wq.y;
                }
                float xs[4] = { kk == 0 ? xv[0].x : kk == 1 ? xv[0].y : kk == 2 ? xv[0].z : xv[0].w,
                                kk == 0 ? xv[1].x : kk == 1 ? xv[1].y : kk == 2 ? xv[1].z : xv[1].w,
                                kk == 0 ? xv[2].x : kk == 1 ? xv[2].y : kk == 2 ? xv[2].z : xv[2].w,
                                kk == 0 ? xv[3].x : kk == 1 ? xv[3].y : kk == 2 ? xv[3].z : xv[3].w };
                #pragma unroll
                for (int t = 0; t < TN; t++)
                    #pragma unroll
                    for (int r = 0; r < 4; r++)
                        acc[r][t] = fmaf(xs[r], wv[t], acc[r][t]);
            }
        }
        #pragma unroll
        for (int r = 0; r < 4; r++) {
            int row = row0 + r;
            if (row < N) {
                float dsr = g_dis[row];
                if (TN == 4) {
                    __half2 p0 = __floats2half2_rn(acc[r][0] * dsr, acc[r][1] * dsr);
                    __half2 p1 = __floats2half2_rn(acc[r][2] * dsr, acc[r][3] * dsr);
                    uint2 st;
                    st.x = *(unsigned*)&p0;
                    st.y = *(unsigned*)&p1;
                    *(uint2*)(O16 + (size_t)row * M + cg * 4) = st;
                } else {
                    __half2 p = __floats2half2_rn(acc[r][0] * dsr, acc[r][1] * dsr);
                    *(__half2*)(O16 + (size_t)row * M + cg * 2) = p;
                }
            }
        }
    }
}

// ---------------------------------------------------------------------------
__global__ void __launch_bounds__(TPB, 5) k_mega(
        const float* __restrict__ x, const void* __restrict__ ei,
        const float* __restrict__ W1, const float* __restrict__ b1,
        const float* __restrict__ W2, const float* __restrict__ b2,
        const float* __restrict__ W3, const float* __restrict__ b3,
        float* __restrict__ out, int N, int E) {
    __shared__ SM sm;
    int gtid = blockIdx.x * TPB + threadIdx.x;
    int lane = threadIdx.x & 31;
    int gwarp = gtid >> 5;

    // warp-parallel dtype detect (first 64 int64 values), per block
    if (threadIdx.x < 32) {
        const long long* p = (const long long*)ei;
        long long v0 = p[threadIdx.x], v1 = p[32 + threadIdx.x];
        int ok = (v0 >= 0 && v0 < (long long)N && v1 >= 0 && v1 < (long long)N);
        unsigned m = __ballot_sync(0xffffffffu, ok);
        if (threadIdx.x == 0) sm.is64 = (m == 0xffffffffu);
    }
    __syncthreads();
    int is64 = sm.is64;

    // Phase A: degree histogram (deg pre-zeroed by previous run)
    for (int e = gtid; e < E; e += NTH)
        atomicAdd(&g_deg[edge_at(ei, (size_t)E + e, is64)], 1);
    gsync(1u * NB);

    // Phase B: warp-aggregated bump allocation (pad to 8) + dis + self-pads
    {
        int nround = ((N + NTH - 1) / NTH) * NTH;
        for (int i = gtid; i < nround; i += NTH) {
            int d = (i < N) ? g_deg[i] : 0;
            int pad = (i < N) ? ((d + 7) & ~7) : 0;
            int incl = pad;
            #pragma unroll
            for (int off = 1; off < 32; off <<= 1) {
                int v = __shfl_up_sync(0xffffffffu, incl, off);
                if (lane >= off) incl += v;
            }
            int total = __shfl_sync(0xffffffffu, incl, 31);
            int base;
            if (lane == 31) base = atomicAdd(&g_alloc, total);
            base = __shfl_sync(0xffffffffu, base, 31);
            if (i < N) {
                int st = base + incl - pad;
                g_rowptr[i] = st;
                g_dis[i] = rsqrtf((float)(d + 1));
                for (int j = d; j < pad; j++) g_csr[st + j] = i;
            }
        }
    }
    gsync(2u * NB);

    // Phase C: GEMM1 (x @ W1 -> fp16, scaled by dis) + CSR fill
    gemm_phase<64, 64>(x, W1, g_h16, N, &sm, 0);
    for (int e = gtid; e < E; e += NTH) {
        int s = edge_at(ei, e, is64);
        int d = edge_at(ei, (size_t)E + e, is64);
        int pos = atomicAdd(&g_cursor[d], 1);
        g_csr[g_rowptr[d] + pos] = s;
    }
    gsync(3u * NB);

    // Phase D: gather1, warp-cooperative: slot = lane>>3 (4 edges/iter),
    //          chunk = lane&7 (8 x uint4 = 64 fp16 per node)
    for (int i = gtid; i < N; i += NTH) g_cursor[i] = 0;   // re-zero for next run
    {
        const uint4* __restrict__ Hq = (const uint4*)g_h16;
        int slot = lane >> 3;
        int chunk = lane & 7;
        for (int n = gwarp; n < N; n += NWARPS) {
            int d = g_deg[n];
            int pad = (d + 7) & ~7;
            int pc = pad >> 2;                 // 4-edge groups
            const int4* __restrict__ C4 = (const int4*)(g_csr + g_rowptr[n]);
            float acc[8] = {0.f, 0.f, 0.f, 0.f, 0.f, 0.f, 0.f, 0.f};
            for (int j = 0; j < pc; j++) {
                int4 a = __ldg(&C4[j]);       // warp-broadcast
                int src = (slot == 0) ? a.x : (slot == 1) ? a.y : (slot == 2) ? a.z : a.w;
                uint4 q = __ldg(&Hq[(size_t)src * 8 + chunk]);
                h8_acc(acc, q);
            }
            // reduce across 4 slots (lanes differ by 8, 16)
            #pragma unroll
            for (int k = 0; k < 8; k++) {
                acc[k] += __shfl_down_sync(0xffffffffu, acc[k], 16);
                acc[k] += __shfl_down_sync(0xffffffffu, acc[k], 8);
            }
            if (slot == 0) {                  // lanes 0..7 hold results
                float coef = 1.0f - (float)(pad - d);
                uint4 qs = __ldg(&Hq[(size_t)n * 8 + chunk]);
                float s[8]; h8_unpack(qs, s);
                float dsn = g_dis[n];
                float4 ba = __ldg(((const float4*)b1) + 2 * chunk);
                float4 bb = __ldg(((const float4*)b1) + 2 * chunk + 1);
                float bv[8] = {ba.x, ba.y, ba.z, ba.w, bb.x, bb.y, bb.z, bb.w};
                float o[8];
                #pragma unroll
                for (int k = 0; k < 8; k++) {
                    float v = fmaf(s[k], coef, acc[k]);
                    o[k] = fast_tanh(fmaf(v, dsn, bv[k]));
                }
                float4* dst = (float4*)(g_o + (size_t)n * 64 + chunk * 8);
                dst[0] = make_float4(o[0], o[1], o[2], o[3]);
                dst[1] = make_float4(o[4], o[5], o[6], o[7]);
            }
        }
    }
    gsync(4u * NB);

    // Phase E: GEMM2 (o1 @ W2 -> fp16, scaled by dis) -> g_h16
    gemm_phase<64, 32>(g_o, W2, g_h16, N, &sm, 1);
    gsync(5u * NB);

    // Phase F: gather2, warp-cooperative: slot = lane>>2 (8 edges/iter),
    //          chunk = lane&3 (4 x uint4 = 32 fp16); fused projection
    {
        const uint4* __restrict__ Hq = (const uint4*)g_h16;
        int slot = lane >> 2;                  // 0..7
        int chunk = lane & 3;                  // 0..3
        for (int n = gwarp; n < N; n += NWARPS) {
            int d = g_deg[n];
            int pad = (d + 7) & ~7;
            int pc = pad >> 3;                 // 8-edge groups
            const int* __restrict__ C = g_csr + g_rowptr[n];
            float acc[8] = {0.f, 0.f, 0.f, 0.f, 0.f, 0.f, 0.f, 0.f};
            for (int j = 0; j < pc; j++) {
                int src = __ldg(&C[j * 8 + slot]);     // 4-lane broadcast groups
                uint4 q = __ldg(&Hq[(size_t)src * 4 + chunk]);
                h8_acc(acc, q);
            }
            // reduce across 8 slots (lanes differ by 4, 8, 16)
            #pragma unroll
            for (int k = 0; k < 8; k++) {
                acc[k] += __shfl_down_sync(0xffffffffu, acc[k], 16);
                acc[k] += __shfl_down_sync(0xffffffffu, acc[k], 8);
                acc[k] += __shfl_down_sync(0xffffffffu, acc[k], 4);
            }
            float partial = 0.f;
            float dsn = g_dis[n];
            if (slot == 0) {                  // lanes 0..3 hold results
                float coef = 1.0f - (float)(pad - d);
                uint4 qs = __ldg(&Hq[(size_t)n * 4 + chunk]);
                float s[8]; h8_unpack(qs, s);
                float4 ba = __ldg(((const float4*)b2) + 2 * chunk);
                float4 bb = __ldg(((const float4*)b2) + 2 * chunk + 1);
                float bv[8] = {ba.x, ba.y, ba.z, ba.w, bb.x, bb.y, bb.z, bb.w};
                float4 wa = __ldg(((const float4*)W3) + 2 * chunk);
                float4 wb = __ldg(((const float4*)W3) + 2 * chunk + 1);
                float wv[8] = {wa.x, wa.y, wa.z, wa.w, wb.x, wb.y, wb.z, wb.w};
                #pragma unroll
                for (int k = 0; k < 8; k++) {
                    float v = fmaf(s[k], coef, acc[k]);
                    partial += fast_tanh(fmaf(v, dsn, bv[k])) * wv[k];
                }
            }
            partial += __shfl_down_sync(0xffffffffu, partial, 2, 4);
            partial += __shfl_down_sync(0xffffffffu, partial, 1, 4);
            if (lane == 0) g_o[n] = dsn * partial;
        }
    }
    gsync(6u * NB);

    // Phase G: scalar gather3; out = dis*(sum + hs3_self) + b3; zero deg
    {
        float bb = __ldg(b3);
        for (int n = gwarp; n < N; n += NWARPS) {
            int start = g_rowptr[n];
            int c = g_deg[n];
            float acc = 0.f;
            for (int j = lane; j < c; j += 32)
                acc += __ldg(&g_o[g_csr[start + j]]);
            #pragma unroll
            for (int off = 16; off; off >>= 1)
                acc += __shfl_down_sync(0xffffffffu, acc, off);
            if (lane == 0) {
                out[n] = fmaf(g_dis[n], acc + g_o[n], bb);
                g_deg[n] = 0;                    // restore invariant
            }
        }
    }

    // final arrival: last CTA resets counters for next graph replay
    __syncthreads();
    if (threadIdx.x == 0) {
        __threadfence();
        unsigned v = atomicAdd(&g_bar, 1u);
        if (v == 7u * NB - 1u) {
            g_bar = 0u; g_alloc = 0;
            g_work[0] = 0; g_work[1] = 0; g_work[2] = 0; g_work[3] = 0;
        }
    }
}

// ---------------------------------------------------------------------------
extern "C" void kernel_launch(void* const* d_in, const int* in_sizes, int n_in,
                              void* d_out, int out_size) {
    const float* x  = (const float*)d_in[0];
    const void*  ei = d_in[1];
    const float* W1 = (const float*)d_in[2];
    const float* b1 = (const float*)d_in[3];
    const float* W2 = (const float*)d_in[4];
    const float* b2 = (const float*)d_in[5];
    const float* W3 = (const float*)d_in[6];
    const float* b3 = (const float*)d_in[7];
    float* out = (float*)d_out;

    int N = in_sizes[0] / 64;
    int E = in_sizes[1] / 2;

    k_mega<<<NB, TPB>>>(x, ei, W1, b1, W2, b2, W3, b3, out, N, E);
}

// round 12
// speedup vs baseline: 1.1912x; 1.1912x over previous
#include <cuda_runtime.h>
#include <cuda_fp16.h>

// ---------------------------------------------------------------------------
// 3-layer GCN persistent megakernel, round 12 (= round 9 + 8-edge gather MLP):
//  - fp16 feature storage, fp32 accumulation; thread-per-(node,lane) gathers
//  - CSR padded to 8 entries (pads = self; coef corrects exactly);
//    gather inner loop: 2 int4 + 8 independent 16B feature loads in flight
//  - fp32 GEMMs w/ dynamic 64-row tiles; warp-agg alloc; deferred zeroing
// ---------------------------------------------------------------------------

#define NMAX 100000
#define EMAX 1600000
#define CSRMAX (EMAX + 8 * NMAX)
#define NB  740          // 148 SMs x 5 CTAs
#define TPB 256
#define NTH (NB * TPB)

__device__ unsigned g_bar;        // zero-init; restored to 0 at exit
__device__ int   g_alloc;         // restored at exit
__device__ int   g_work[8];       // GEMM tile counters; restored at exit
__device__ int   g_deg[NMAX];     // zeroed by previous run's final phase
__device__ int   g_rowptr[NMAX];
__device__ int   g_cursor[NMAX];  // zeroed by previous run's gather1 phase
__device__ float g_dis[NMAX];
__device__ __align__(16) int g_csr[CSRMAX];     // src indices; pads = dst itself
__device__ __align__(16) __half g_h16[(size_t)NMAX * 64];  // fp16 features
__device__ float g_o[(size_t)NMAX * 64];

struct SM {
    __align__(16) float w[4096];
    int tile;
    int is64;
};

__device__ __forceinline__ float fast_tanh(float x) {
    float y;
    asm("tanh.approx.f32 %0, %1;" : "=f"(y) : "f"(x));
    return y;
}

__device__ __forceinline__ void gsync(unsigned target) {
    __syncthreads();
    if (threadIdx.x == 0) {
        __threadfence();
        atomicAdd(&g_bar, 1u);
        while (*((volatile unsigned*)&g_bar) < target) __nanosleep(64);
    }
    __syncthreads();
}

__device__ __forceinline__ int edge_at(const void* ei, size_t idx, int is64) {
    if (is64) return (int)((const long long*)ei)[idx];
    return ((const int*)ei)[idx];
}

__device__ __forceinline__ void h8_acc(float* acc, uint4 q) {
    float2 t;
    t = __half22float2(*(__half2*)&q.x); acc[0] += t.x; acc[1] += t.y;
    t = __half22float2(*(__half2*)&q.y); acc[2] += t.x; acc[3] += t.y;
    t = __half22float2(*(__half2*)&q.z); acc[4] += t.x; acc[5] += t.y;
    t = __half22float2(*(__half2*)&q.w); acc[6] += t.x; acc[7] += t.y;
}
__device__ __forceinline__ void h8_unpack(uint4 q, float* f) {
    float2 t;
    t = __half22float2(*(__half2*)&q.x); f[0] = t.x; f[1] = t.y;
    t = __half22float2(*(__half2*)&q.y); f[2] = t.x; f[3] = t.y;
    t = __half22float2(*(__half2*)&q.z); f[4] = t.x; f[5] = t.y;
    t = __half22float2(*(__half2*)&q.w); f[6] = t.x; f[7] = t.y;
}

// ---- GEMM: O16[N,M] = fp16( dis[row] * (X[N,K] @ W[K,M]) ), dyn 64-row tiles
template <int K, int M>
__device__ void gemm_phase(const float* __restrict__ X, const float* __restrict__ W,
                           __half* __restrict__ O16, int N, SM* sm, int workid) {
    constexpr int TN = M / 16;
    for (int i = threadIdx.x; i < K * M; i += TPB) sm->w[i] = W[i];
    int cg = threadIdx.x & 15;
    int rg = threadIdx.x >> 4;
    int tiles = (N + 63) >> 6;
    const float4* __restrict__ X4 = (const float4*)X;
    for (;;) {
        __syncthreads();
        if (threadIdx.x == 0) sm->tile = atomicAdd(&g_work[workid], 1);
        __syncthreads();
        int tile = sm->tile;
        if (tile >= tiles) break;
        int row0 = tile * 64 + rg * 4;
        bool full = (row0 + 3 < N);
        float acc[4][TN];
        #pragma unroll
        for (int r = 0; r < 4; r++)
            #pragma unroll
            for (int t = 0; t < TN; t++) acc[r][t] = 0.f;
        #pragma unroll 2
        for (int k4 = 0; k4 < K / 4; k4++) {
            float4 xv[4];
            #pragma unroll
            for (int r = 0; r < 4; r++) {
                int row = row0 + r;
                if (full || row < N) xv[r] = __ldg(&X4[(size_t)row * (K / 4) + k4]);
                else xv[r] = make_float4(0.f, 0.f, 0.f, 0.f);
            }
            #pragma unroll
            for (int kk = 0; kk < 4; kk++) {
                int k = k4 * 4 + kk;
                float wv[TN];
                if (TN == 4) {
                    float4 wq = ((const float4*)sm->w)[k * (M / 4) + cg];
                    wv[0] = wq.x; wv[1] = wq.y; wv[2] = wq.z; wv[3] = wq.w;
                } else {
                    float2 wq = ((const float2*)sm->w)[k * (M / 2) + cg];
                    wv[0] = wq.x; wv[1] = wq.y;
                }
                float xs[4] = { kk == 0 ? xv[0].x : kk == 1 ? xv[0].y : kk == 2 ? xv[0].z : xv[0].w,
                                kk == 0 ? xv[1].x : kk == 1 ? xv[1].y : kk == 2 ? xv[1].z : xv[1].w,
                                kk == 0 ? xv[2].x : kk == 1 ? xv[2].y : kk == 2 ? xv[2].z : xv[2].w,
                                kk == 0 ? xv[3].x : kk == 1 ? xv[3].y : kk == 2 ? xv[3].z : xv[3].w };
                #pragma unroll
                for (int t = 0; t < TN; t++)
                    #pragma unroll
                    for (int r = 0; r < 4; r++)
                        acc[r][t] = fmaf(xs[r], wv[t], acc[r][t]);
            }
        }
        #pragma unroll
        for (int r = 0; r < 4; r++) {
            int row = row0 + r;
            if (row < N) {
                float dsr = g_dis[row];
                if (TN == 4) {
                    __half2 p0 = __floats2half2_rn(acc[r][0] * dsr, acc[r][1] * dsr);
                    __half2 p1 = __floats2half2_rn(acc[r][2] * dsr, acc[r][3] * dsr);
                    uint2 st;
                    st.x = *(unsigned*)&p0;
                    st.y = *(unsigned*)&p1;
                    *(uint2*)(O16 + (size_t)row * M + cg * 4) = st;
                } else {
                    __half2 p = __floats2half2_rn(acc[r][0] * dsr, acc[r][1] * dsr);
                    *(__half2*)(O16 + (size_t)row * M + cg * 2) = p;
                }
            }
        }
    }
}

// ---------------------------------------------------------------------------
__global__ void __launch_bounds__(TPB, 5) k_mega(
        const float* __restrict__ x, const void* __restrict__ ei,
        const float* __restrict__ W1, const float* __restrict__ b1,
        const float* __restrict__ W2, const float* __restrict__ b2,
        const float* __restrict__ W3, const float* __restrict__ b3,
        float* __restrict__ out, int N, int E) {
    __shared__ SM sm;
    int gtid = blockIdx.x * TPB + threadIdx.x;
    int lane = threadIdx.x & 31;

    // warp-parallel dtype detect (first 64 int64 values), per block
    if (threadIdx.x < 32) {
        const long long* p = (const long long*)ei;
        long long v0 = p[threadIdx.x], v1 = p[32 + threadIdx.x];
        int ok = (v0 >= 0 && v0 < (long long)N && v1 >= 0 && v1 < (long long)N);
        unsigned m = __ballot_sync(0xffffffffu, ok);
        if (threadIdx.x == 0) sm.is64 = (m == 0xffffffffu);
    }
    __syncthreads();
    int is64 = sm.is64;

    // Phase A: degree histogram (deg pre-zeroed by previous run)
    for (int e = gtid; e < E; e += NTH)
        atomicAdd(&g_deg[edge_at(ei, (size_t)E + e, is64)], 1);
    gsync(1u * NB);

    // Phase B: warp-aggregated bump allocation (pad to 8) + dis + self-pads
    {
        int nround = ((N + NTH - 1) / NTH) * NTH;
        for (int i = gtid; i < nround; i += NTH) {
            int d = (i < N) ? g_deg[i] : 0;
            int pad = (i < N) ? ((d + 7) & ~7) : 0;
            int incl = pad;
            #pragma unroll
            for (int off = 1; off < 32; off <<= 1) {
                int v = __shfl_up_sync(0xffffffffu, incl, off);
                if (lane >= off) incl += v;
            }
            int total = __shfl_sync(0xffffffffu, incl, 31);
            int base;
            if (lane == 31) base = atomicAdd(&g_alloc, total);
            base = __shfl_sync(0xffffffffu, base, 31);
            if (i < N) {
                int st = base + incl - pad;
                g_rowptr[i] = st;
                g_dis[i] = rsqrtf((float)(d + 1));
                for (int j = d; j < pad; j++) g_csr[st + j] = i;
            }
        }
    }
    gsync(2u * NB);

    // Phase C: GEMM1 (x @ W1 -> fp16, scaled by dis) + CSR fill
    gemm_phase<64, 64>(x, W1, g_h16, N, &sm, 0);
    for (int e = gtid; e < E; e += NTH) {
        int s = edge_at(ei, e, is64);
        int d = edge_at(ei, (size_t)E + e, is64);
        int pos = atomicAdd(&g_cursor[d], 1);
        g_csr[g_rowptr[d] + pos] = s;
    }
    gsync(3u * NB);

    // Phase D: gather1 (fp16 in, fp32 accum), 8 lanes/node, 8 edges in flight
    for (int i = gtid; i < N; i += NTH) g_cursor[i] = 0;   // re-zero for next run
    {
        const uint4* __restrict__ Hq = (const uint4*)g_h16;   // 8 uint4 per node
        long long items = (long long)N * 8;
        for (long long it = gtid; it < items; it += NTH) {
            int node = (int)(it >> 3);
            int l = (int)(it & 7);
            int d = g_deg[node];
            int pad = (d + 7) & ~7;
            int pc = pad >> 3;                    // 8-edge groups
            float coef = 1.0f - (float)(pad - d);
            const int4* __restrict__ C4 = (const int4*)(g_csr + g_rowptr[node]);
            float acc[8] = {0.f, 0.f, 0.f, 0.f, 0.f, 0.f, 0.f, 0.f};
            for (int j = 0; j < pc; j++) {
                int4 a = __ldg(&C4[2 * j]);
                int4 b = __ldg(&C4[2 * j + 1]);
                uint4 q0 = __ldg(&Hq[(size_t)a.x * 8 + l]);
                uint4 q1 = __ldg(&Hq[(size_t)a.y * 8 + l]);
                uint4 q2 = __ldg(&Hq[(size_t)a.z * 8 + l]);
                uint4 q3 = __ldg(&Hq[(size_t)a.w * 8 + l]);
                uint4 q4 = __ldg(&Hq[(size_t)b.x * 8 + l]);
                uint4 q5 = __ldg(&Hq[(size_t)b.y * 8 + l]);
                uint4 q6 = __ldg(&Hq[(size_t)b.z * 8 + l]);
                uint4 q7 = __ldg(&Hq[(size_t)b.w * 8 + l]);
                h8_acc(acc, q0); h8_acc(acc, q1); h8_acc(acc, q2); h8_acc(acc, q3);
                h8_acc(acc, q4); h8_acc(acc, q5); h8_acc(acc, q6); h8_acc(acc, q7);
            }
            uint4 qs = __ldg(&Hq[(size_t)node * 8 + l]);
            float s[8]; h8_unpack(qs, s);
            #pragma unroll
            for (int k = 0; k < 8; k++) acc[k] = fmaf(s[k], coef, acc[k]);
            float dsn = g_dis[node];
            float4 ba = __ldg(((const float4*)b1) + 2 * l);
            float4 bb = __ldg(((const float4*)b1) + 2 * l + 1);
            float bv[8] = {ba.x, ba.y, ba.z, ba.w, bb.x, bb.y, bb.z, bb.w};
            float o[8];
            #pragma unroll
            for (int k = 0; k < 8; k++) o[k] = fast_tanh(fmaf(acc[k], dsn, bv[k]));
            float4* dst = (float4*)(g_o + (size_t)node * 64 + l * 8);
            dst[0] = make_float4(o[0], o[1], o[2], o[3]);
            dst[1] = make_float4(o[4], o[5], o[6], o[7]);
        }
    }
    gsync(4u * NB);

    // Phase E: GEMM2 (o1 @ W2 -> fp16, scaled by dis) -> g_h16
    gemm_phase<64, 32>(g_o, W2, g_h16, N, &sm, 1);
    gsync(5u * NB);

    // Phase F: gather2 + tanh + fused projection; 4 lanes/node, 8 edges in flight
    {
        const uint4* __restrict__ Hq = (const uint4*)g_h16;   // 4 uint4 per node
        long long items = (long long)N * 4;
        for (long long it = gtid; it < items; it += NTH) {
            int node = (int)(it >> 2);
            int l = (int)(it & 3);
            int d = g_deg[node];
            int pad = (d + 7) & ~7;
            int pc = pad >> 3;
            float coef = 1.0f - (float)(pad - d);
            const int4* __restrict__ C4 = (const int4*)(g_csr + g_rowptr[node]);
            float acc[8] = {0.f, 0.f, 0.f, 0.f, 0.f, 0.f, 0.f, 0.f};
            for (int j = 0; j < pc; j++) {
                int4 a = __ldg(&C4[2 * j]);
                int4 b = __ldg(&C4[2 * j + 1]);
                uint4 q0 = __ldg(&Hq[(size_t)a.x * 4 + l]);
                uint4 q1 = __ldg(&Hq[(size_t)a.y * 4 + l]);
                uint4 q2 = __ldg(&Hq[(size_t)a.z * 4 + l]);
                uint4 q3 = __ldg(&Hq[(size_t)a.w * 4 + l]);
                uint4 q4 = __ldg(&Hq[(size_t)b.x * 4 + l]);
                uint4 q5 = __ldg(&Hq[(size_t)b.y * 4 + l]);
                uint4 q6 = __ldg(&Hq[(size_t)b.z * 4 + l]);
                uint4 q7 = __ldg(&Hq[(size_t)b.w * 4 + l]);
                h8_acc(acc, q0); h8_acc(acc, q1); h8_acc(acc, q2); h8_acc(acc, q3);
                h8_acc(acc, q4); h8_acc(acc, q5); h8_acc(acc, q6); h8_acc(acc, q7);
            }
            uint4 qs = __ldg(&Hq[(size_t)node * 4 + l]);
            float s[8]; h8_unpack(qs, s);
            #pragma unroll
            for (int k = 0; k < 8; k++) acc[k] = fmaf(s[k], coef, acc[k]);
            float dsn = g_dis[node];
            float4 ba = __ldg(((const float4*)b2) + 2 * l);
            float4 bb = __ldg(((const float4*)b2) + 2 * l + 1);
            float bv[8] = {ba.x, ba.y, ba.z, ba.w, bb.x, bb.y, bb.z, bb.w};
            float4 wa = __ldg(((const float4*)W3) + 2 * l);
            float4 wb = __ldg(((const float4*)W3) + 2 * l + 1);
            float wv[8] = {wa.x, wa.y, wa.z, wa.w, wb.x, wb.y, wb.z, wb.w};
            float partial = 0.f;
            #pragma unroll
            for (int k = 0; k < 8; k++)
                partial += fast_tanh(fmaf(acc[k], dsn, bv[k])) * wv[k];
            partial += __shfl_down_sync(0xffffffffu, partial, 2, 4);
            partial += __shfl_down_sync(0xffffffffu, partial, 1, 4);
            if (l == 0) g_o[node] = dsn * partial;
        }
    }
    gsync(6u * NB);

    // Phase G: scalar gather3; out = dis*(sum + hs3_self) + b3; zero deg
    {
        float bb = __ldg(b3);
        int wg = gtid >> 5;
        for (int n = wg; n < N; n += (NTH >> 5)) {
            int start = g_rowptr[n];
            int c = g_deg[n];
            float acc = 0.f;
            for (int j = lane; j < c; j += 32)
                acc += __ldg(&g_o[g_csr[start + j]]);
            #pragma unroll
            for (int off = 16; off; off >>= 1)
                acc += __shfl_down_sync(0xffffffffu, acc, off);
            if (lane == 0) {
                out[n] = fmaf(g_dis[n], acc + g_o[n], bb);
                g_deg[n] = 0;                    // restore invariant
            }
        }
    }

    // final arrival: last CTA resets counters for next graph replay
    __syncthreads();
    if (threadIdx.x == 0) {
        __threadfence();
        unsigned v = atomicAdd(&g_bar, 1u);
        if (v == 7u * NB - 1u) {
            g_bar = 0u; g_alloc = 0;
            g_work[0] = 0; g_work[1] = 0; g_work[2] = 0; g_work[3] = 0;
        }
    }
}

// ---------------------------------------------------------------------------
extern "C" void kernel_launch(void* const* d_in, const int* in_sizes, int n_in,
                              void* d_out, int out_size) {
    const float* x  = (const float*)d_in[0];
    const void*  ei = d_in[1];
    const float* W1 = (const float*)d_in[2];
    const float* b1 = (const float*)d_in[3];
    const float* W2 = (const float*)d_in[4];
    const float* b2 = (const float*)d_in[5];
    const float* W3 = (const float*)d_in[6];
    const float* b3 = (const float*)d_in[7];
    float* out = (float*)d_out;

    int N = in_sizes[0] / 64;
    int E = in_sizes[1] / 2;

    k_mega<<<NB, TPB>>>(x, ei, W1, b1, W2, b2, W3, b3, out, N, E);
}

// round 13
// speedup vs baseline: 1.6021x; 1.3450x over previous
#include <cuda_runtime.h>
#include <cuda_fp16.h>

// ---------------------------------------------------------------------------
// 3-layer GCN persistent megakernel, round 13 (= round 9 + tensor-core GEMMs):
//  - GEMMs via mma.sync m16n8k16 (fp16 in, fp32 accum), dis-scale fused,
//    fp16 outputs; x converted to fp16 in phase A (overlapped w/ degree)
//  - o1 stored fp16 (feeds GEMM2 directly)
//  - gathers: round-9 shape (thread-per-(node,lane), 4-edge groups, pad-4)
//  - warp-agg alloc, deferred zeroing, 7 global barriers
// ---------------------------------------------------------------------------

#define NMAX 100000
#define EMAX 1600000
#define CSRMAX (EMAX + 4 * NMAX)
#define NB  740          // 148 SMs x 5 CTAs
#define TPB 256
#define NTH (NB * TPB)
#define NWARPS (NTH >> 5)

__device__ unsigned g_bar;        // zero-init; restored to 0 at exit
__device__ int   g_alloc;         // restored at exit
__device__ int   g_deg[NMAX];     // zeroed by previous run's final phase
__device__ int   g_rowptr[NMAX];
__device__ int   g_cursor[NMAX];  // zeroed by previous run's gather1 phase
__device__ float g_dis[NMAX];
__device__ float g_s[NMAX];       // scalar hs3 per node
__device__ __align__(16) int g_csr[CSRMAX];     // src indices; pads = dst itself
__device__ __align__(16) __half g_x16[(size_t)NMAX * 64];  // fp16 input features
__device__ __align__(16) __half g_h16[(size_t)NMAX * 64];  // fp16 GEMM outputs
__device__ __align__(16) __half g_o16[(size_t)NMAX * 64];  // fp16 o1 activations

struct SM {
    __align__(16) float w[4096];   // aliased as __half2 for fragment packs
    int is64;
};

__device__ __forceinline__ float fast_tanh(float x) {
    float y;
    asm("tanh.approx.f32 %0, %1;" : "=f"(y) : "f"(x));
    return y;
}

__device__ __forceinline__ void gsync(unsigned target) {
    __syncthreads();
    if (threadIdx.x == 0) {
        __threadfence();
        atomicAdd(&g_bar, 1u);
        while (*((volatile unsigned*)&g_bar) < target) __nanosleep(64);
    }
    __syncthreads();
}

__device__ __forceinline__ int edge_at(const void* ei, size_t idx, int is64) {
    if (is64) return (int)((const long long*)ei)[idx];
    return ((const int*)ei)[idx];
}

__device__ __forceinline__ void h8_acc(float* acc, uint4 q) {
    float2 t;
    t = __half22float2(*(__half2*)&q.x); acc[0] += t.x; acc[1] += t.y;
    t = __half22float2(*(__half2*)&q.y); acc[2] += t.x; acc[3] += t.y;
    t = __half22float2(*(__half2*)&q.z); acc[4] += t.x; acc[5] += t.y;
    t = __half22float2(*(__half2*)&q.w); acc[6] += t.x; acc[7] += t.y;
}
__device__ __forceinline__ void h8_unpack(uint4 q, float* f) {
    float2 t;
    t = __half22float2(*(__half2*)&q.x); f[0] = t.x; f[1] = t.y;
    t = __half22float2(*(__half2*)&q.y); f[2] = t.x; f[3] = t.y;
    t = __half22float2(*(__half2*)&q.z); f[4] = t.x; f[5] = t.y;
    t = __half22float2(*(__half2*)&q.w); f[6] = t.x; f[7] = t.y;
}

__device__ __forceinline__ void mma16816(
        float& c0, float& c1, float& c2, float& c3,
        unsigned a0, unsigned a1, unsigned a2, unsigned a3,
        unsigned b0, unsigned b1) {
    asm volatile(
        "mma.sync.aligned.m16n8k16.row.col.f32.f16.f16.f32 "
        "{%0,%1,%2,%3}, {%4,%5,%6,%7}, {%8,%9}, {%0,%1,%2,%3};"
        : "+f"(c0), "+f"(c1), "+f"(c2), "+f"(c3)
        : "r"(a0), "r"(a1), "r"(a2), "r"(a3), "r"(b0), "r"(b1));
}

// ---- tensor GEMM: O16[N,M] = fp16( dis[row] * (Xh[N,64] @ W[64,M]) ) -------
// W packed into B-fragment layout in smem: wp[((ks*2+h)*M + col)*4 + tg]
//   = half2( W[ks*16+h*8+tg*2][col], W[ks*16+h*8+tg*2+1][col] )
template <int M>
__device__ void gemm_mma(const __half* __restrict__ Xh, const float* __restrict__ W,
                         __half* __restrict__ O16, int N, SM* sm, int gwarp) {
    __half2* wp = (__half2*)sm->w;
    const int entries = 4 * 2 * M * 4;
    for (int idx = threadIdx.x; idx < entries; idx += TPB) {
        int tg = idx & 3;
        int col = (idx >> 2) % M;
        int rest = (idx >> 2) / M;
        int h = rest & 1, ks = rest >> 1;
        int k0 = ks * 16 + h * 8 + tg * 2;
        wp[idx] = __floats2half2_rn(W[k0 * M + col], W[(k0 + 1) * M + col]);
    }
    __syncthreads();
    int lane = threadIdx.x & 31;
    int g = lane >> 2, tg = lane & 3;
    int tiles = (N + 15) >> 4;
    for (int t = gwarp; t < tiles; t += NWARPS) {
        int rlo = t * 16 + g;
        int rhi = rlo + 8;
        bool oklo = rlo < N, okhi = rhi < N;
        #pragma unroll
        for (int cc = 0; cc < M / 32; cc++) {
            float c[4][4];
            #pragma unroll
            for (int nt = 0; nt < 4; nt++)
                #pragma unroll
                for (int q = 0; q < 4; q++) c[nt][q] = 0.f;
            #pragma unroll
            for (int ks = 0; ks < 4; ks++) {
                unsigned a0 = 0, a1 = 0, a2 = 0, a3 = 0;
                if (oklo) {
                    const __half* p = Xh + (size_t)rlo * 64 + ks * 16 + tg * 2;
                    a0 = *(const unsigned*)p;
                    a2 = *(const unsigned*)(p + 8);
                }
                if (okhi) {
                    const __half* p = Xh + (size_t)rhi * 64 + ks * 16 + tg * 2;
                    a1 = *(const unsigned*)p;
                    a3 = *(const unsigned*)(p + 8);
                }
                #pragma unroll
                for (int nt = 0; nt < 4; nt++) {
                    int col = cc * 32 + nt * 8 + g;
                    unsigned b0 = *(unsigned*)&wp[((ks * 2 + 0) * M + col) * 4 + tg];
                    unsigned b1 = *(unsigned*)&wp[((ks * 2 + 1) * M + col) * 4 + tg];
                    mma16816(c[nt][0], c[nt][1], c[nt][2], c[nt][3],
                             a0, a1, a2, a3, b0, b1);
                }
            }
            float dlo = oklo ? g_dis[rlo] : 0.f;
            float dhi = okhi ? g_dis[rhi] : 0.f;
            #pragma unroll
            for (int nt = 0; nt < 4; nt++) {
                int colst = cc * 32 + nt * 8 + tg * 2;
                if (oklo) {
                    __half2 v = __floats2half2_rn(c[nt][0] * dlo, c[nt][1] * dlo);
                    *(__half2*)(O16 + (size_t)rlo * M + colst) = v;
                }
                if (okhi) {
                    __half2 v = __floats2half2_rn(c[nt][2] * dhi, c[nt][3] * dhi);
                    *(__half2*)(O16 + (size_t)rhi * M + colst) = v;
                }
            }
        }
    }
}

// ---------------------------------------------------------------------------
__global__ void __launch_bounds__(TPB, 5) k_mega(
        const float* __restrict__ x, const void* __restrict__ ei,
        const float* __restrict__ W1, const float* __restrict__ b1,
        const float* __restrict__ W2, const float* __restrict__ b2,
        const float* __restrict__ W3, const float* __restrict__ b3,
        float* __restrict__ out, int N, int E) {
    __shared__ SM sm;
    int gtid = blockIdx.x * TPB + threadIdx.x;
    int lane = threadIdx.x & 31;
    int gwarp = gtid >> 5;

    // warp-parallel dtype detect (first 64 int64 values), per block
    if (threadIdx.x < 32) {
        const long long* p = (const long long*)ei;
        long long v0 = p[threadIdx.x], v1 = p[32 + threadIdx.x];
        int ok = (v0 >= 0 && v0 < (long long)N && v1 >= 0 && v1 < (long long)N);
        unsigned m = __ballot_sync(0xffffffffu, ok);
        if (threadIdx.x == 0) sm.is64 = (m == 0xffffffffu);
    }
    __syncthreads();
    int is64 = sm.is64;

    // Phase A: convert x -> fp16 (independent) + degree histogram
    {
        long long items = (long long)N * 8;
        for (long long i = gtid; i < items; i += NTH) {
            const float4* xs = (const float4*)(x + i * 8);
            float4 u = __ldg(xs), v = __ldg(xs + 1);
            __half2 h0 = __floats2half2_rn(u.x, u.y);
            __half2 h1 = __floats2half2_rn(u.z, u.w);
            __half2 h2 = __floats2half2_rn(v.x, v.y);
            __half2 h3 = __floats2half2_rn(v.z, v.w);
            uint4 st;
            st.x = *(unsigned*)&h0; st.y = *(unsigned*)&h1;
            st.z = *(unsigned*)&h2; st.w = *(unsigned*)&h3;
            ((uint4*)g_x16)[i] = st;
        }
    }
    for (int e = gtid; e < E; e += NTH)
        atomicAdd(&g_deg[edge_at(ei, (size_t)E + e, is64)], 1);
    gsync(1u * NB);

    // Phase B: warp-aggregated bump allocation (pad to 4) + dis + self-pads
    {
        int nround = ((N + NTH - 1) / NTH) * NTH;
        for (int i = gtid; i < nround; i += NTH) {
            int d = (i < N) ? g_deg[i] : 0;
            int pad = (i < N) ? ((d + 3) & ~3) : 0;
            int incl = pad;
            #pragma unroll
            for (int off = 1; off < 32; off <<= 1) {
                int v = __shfl_up_sync(0xffffffffu, incl, off);
                if (lane >= off) incl += v;
            }
            int total = __shfl_sync(0xffffffffu, incl, 31);
            int base;
            if (lane == 31) base = atomicAdd(&g_alloc, total);
            base = __shfl_sync(0xffffffffu, base, 31);
            if (i < N) {
                int st = base + incl - pad;
                g_rowptr[i] = st;
                g_dis[i] = rsqrtf((float)(d + 1));
                for (int j = d; j < pad; j++) g_csr[st + j] = i;
            }
        }
    }
    gsync(2u * NB);

    // Phase C: GEMM1 (tensor core, g_x16 @ W1 -> g_h16 scaled) + CSR fill
    gemm_mma<64>(g_x16, W1, g_h16, N, &sm, gwarp);
    for (int e = gtid; e < E; e += NTH) {
        int s = edge_at(ei, e, is64);
        int d = edge_at(ei, (size_t)E + e, is64);
        int pos = atomicAdd(&g_cursor[d], 1);
        g_csr[g_rowptr[d] + pos] = s;
    }
    gsync(3u * NB);

    // Phase D: gather1 (fp16 in, fp32 accum) -> o1 fp16; 8 lanes/node
    for (int i = gtid; i < N; i += NTH) g_cursor[i] = 0;   // re-zero for next run
    {
        const uint4* __restrict__ Hq = (const uint4*)g_h16;   // 8 uint4 per node
        long long items = (long long)N * 8;
        for (long long it = gtid; it < items; it += NTH) {
            int node = (int)(it >> 3);
            int l = (int)(it & 7);
            int d = g_deg[node];
            int pc = (d + 3) >> 2;
            float coef = 1.0f - (float)((pc << 2) - d);
            const int4* __restrict__ C4 = (const int4*)(g_csr + g_rowptr[node]);
            float acc[8] = {0.f, 0.f, 0.f, 0.f, 0.f, 0.f, 0.f, 0.f};
            for (int j = 0; j < pc; j++) {
                int4 a = __ldg(&C4[j]);
                uint4 q0 = __ldg(&Hq[(size_t)a.x * 8 + l]);
                uint4 q1 = __ldg(&Hq[(size_t)a.y * 8 + l]);
                uint4 q2 = __ldg(&Hq[(size_t)a.z * 8 + l]);
                uint4 q3 = __ldg(&Hq[(size_t)a.w * 8 + l]);
                h8_acc(acc, q0); h8_acc(acc, q1); h8_acc(acc, q2); h8_acc(acc, q3);
            }
            uint4 qs = __ldg(&Hq[(size_t)node * 8 + l]);
            float s[8]; h8_unpack(qs, s);
            #pragma unroll
            for (int k = 0; k < 8; k++) acc[k] = fmaf(s[k], coef, acc[k]);
            float dsn = g_dis[node];
            float4 ba = __ldg(((const float4*)b1) + 2 * l);
            float4 bb = __ldg(((const float4*)b1) + 2 * l + 1);
            float bv[8] = {ba.x, ba.y, ba.z, ba.w, bb.x, bb.y, bb.z, bb.w};
            float o[8];
            #pragma unroll
            for (int k = 0; k < 8; k++) o[k] = fast_tanh(fmaf(acc[k], dsn, bv[k]));
            __half2 p0 = __floats2half2_rn(o[0], o[1]);
            __half2 p1 = __floats2half2_rn(o[2], o[3]);
            __half2 p2 = __floats2half2_rn(o[4], o[5]);
            __half2 p3 = __floats2half2_rn(o[6], o[7]);
            uint4 st;
            st.x = *(unsigned*)&p0; st.y = *(unsigned*)&p1;
            st.z = *(unsigned*)&p2; st.w = *(unsigned*)&p3;
            ((uint4*)g_o16)[(size_t)node * 8 + l] = st;
        }
    }
    gsync(4u * NB);

    // Phase E: GEMM2 (tensor core, g_o16 @ W2 -> g_h16 scaled, M=32)
    gemm_mma<32>(g_o16, W2, g_h16, N, &sm, gwarp);
    gsync(5u * NB);

    // Phase F: gather2 + tanh + fused projection; 4 lanes/node -> g_s
    {
        const uint4* __restrict__ Hq = (const uint4*)g_h16;   // 4 uint4 per node
        long long items = (long long)N * 4;
        for (long long it = gtid; it < items; it += NTH) {
            int node = (int)(it >> 2);
            int l = (int)(it & 3);
            int d = g_deg[node];
            int pc = (d + 3) >> 2;
            float coef = 1.0f - (float)((pc << 2) - d);
            const int4* __restrict__ C4 = (const int4*)(g_csr + g_rowptr[node]);
            float acc[8] = {0.f, 0.f, 0.f, 0.f, 0.f, 0.f, 0.f, 0.f};
            for (int j = 0; j < pc; j++) {
                int4 a = __ldg(&C4[j]);
                uint4 q0 = __ldg(&Hq[(size_t)a.x * 4 + l]);
                uint4 q1 = __ldg(&Hq[(size_t)a.y * 4 + l]);
                uint4 q2 = __ldg(&Hq[(size_t)a.z * 4 + l]);
                uint4 q3 = __ldg(&Hq[(size_t)a.w * 4 + l]);
                h8_acc(acc, q0); h8_acc(acc, q1); h8_acc(acc, q2); h8_acc(acc, q3);
            }
            uint4 qs = __ldg(&Hq[(size_t)node * 4 + l]);
            float s[8]; h8_unpack(qs, s);
            #pragma unroll
            for (int k = 0; k < 8; k++) acc[k] = fmaf(s[k], coef, acc[k]);
            float dsn = g_dis[node];
            float4 ba = __ldg(((const float4*)b2) + 2 * l);
            float4 bb = __ldg(((const float4*)b2) + 2 * l + 1);
            float bv[8] = {ba.x, ba.y, ba.z, ba.w, bb.x, bb.y, bb.z, bb.w};
            float4 wa = __ldg(((const float4*)W3) + 2 * l);
            float4 wb = __ldg(((const float4*)W3) + 2 * l + 1);
            float wv[8] = {wa.x, wa.y, wa.z, wa.w, wb.x, wb.y, wb.z, wb.w};
            float partial = 0.f;
            #pragma unroll
            for (int k = 0; k < 8; k++)
                partial += fast_tanh(fmaf(acc[k], dsn, bv[k])) * wv[k];
            partial += __shfl_down_sync(0xffffffffu, partial, 2, 4);
            partial += __shfl_down_sync(0xffffffffu, partial, 1, 4);
            if (l == 0) g_s[node] = dsn * partial;
        }
    }
    gsync(6u * NB);

    // Phase G: scalar gather3; out = dis*(sum + hs3_self) + b3; zero deg
    {
        float bb = __ldg(b3);
        for (int n = gwarp; n < N; n += NWARPS) {
            int start = g_rowptr[n];
            int c = g_deg[n];
            float acc = 0.f;
            for (int j = lane; j < c; j += 32)
                acc += __ldg(&g_s[g_csr[start + j]]);
            #pragma unroll
            for (int off = 16; off; off >>= 1)
                acc += __shfl_down_sync(0xffffffffu, acc, off);
            if (lane == 0) {
                out[n] = fmaf(g_dis[n], acc + g_s[n], bb);
                g_deg[n] = 0;                    // restore invariant
            }
        }
    }

    // final arrival: last CTA resets counters for next graph replay
    __syncthreads();
    if (threadIdx.x == 0) {
        __threadfence();
        unsigned v = atomicAdd(&g_bar, 1u);
        if (v == 7u * NB - 1u) {
            g_bar = 0u; g_alloc = 0;
        }
    }
}

// ---------------------------------------------------------------------------
extern "C" void kernel_launch(void* const* d_in, const int* in_sizes, int n_in,
                              void* d_out, int out_size) {
    const float* x  = (const float*)d_in[0];
    const void*  ei = d_in[1];
    const float* W1 = (const float*)d_in[2];
    const float* b1 = (const float*)d_in[3];
    const float* W2 = (const float*)d_in[4];
    const float* b2 = (const float*)d_in[5];
    const float* W3 = (const float*)d_in[6];
    const float* b3 = (const float*)d_in[7];
    float* out = (float*)d_out;

    int N = in_sizes[0] / 64;
    int E = in_sizes[1] / 2;

    k_mega<<<NB, TPB>>>(x, ei, W1, b1, W2, b2, W3, b3, out, N, E);
}

// round 14
// speedup vs baseline: 1.7409x; 1.0866x over previous
#include <cuda_runtime.h>
#include <cuda_fp16.h>

// ---------------------------------------------------------------------------
// 3-layer GCN persistent megakernel, round 14 (= round 13 + single-pass CSR):
//  - fixed-stride CSR (32 slots/node), built in ONE edge pass; counter = degree
//  - overflow list for deg>32 (rare), scanned by gathers on a rare branch
//  - inputs pre-scaled by dis (x16s = fp16(dis*x), o1s = dis*tanh(...)):
//    row scaling commutes through GEMMs -> GEMMs need no dis at all
//  - tensor-core GEMMs (m16n8k16, fp16 in / fp32 accum), round-9 gather shape
// ---------------------------------------------------------------------------

#define NMAX 100000
#define EMAX 1600000
#define SLOTS 32
#define NB  740          // 148 SMs x 5 CTAs
#define TPB 256
#define NTH (NB * TPB)
#define NWARPS (NTH >> 5)

__device__ unsigned g_bar;        // zero-init; restored to 0 at exit
__device__ int   g_ovfn;          // overflow count; restored at exit
__device__ int   g_deg[NMAX];     // fill counter == degree; zeroed in last phase
__device__ float g_dis[NMAX];
__device__ float g_s[NMAX];       // scalar hs3 per node
__device__ __align__(16) int  g_csr32[(size_t)NMAX * SLOTS];  // fixed-stride CSR
__device__ __align__(16) int2 g_ovf[EMAX];                    // (dst, src) overflow
__device__ __align__(16) __half g_x16[(size_t)NMAX * 64];  // fp16 dis*x
__device__ __align__(16) __half g_h16[(size_t)NMAX * 64];  // fp16 GEMM outputs
__device__ __align__(16) __half g_o16[(size_t)NMAX * 64];  // fp16 dis*o1

struct SM {
    __align__(16) float w[4096];   // aliased as __half2 for B-fragment packs
    int is64;
};

__device__ __forceinline__ float fast_tanh(float x) {
    float y;
    asm("tanh.approx.f32 %0, %1;" : "=f"(y) : "f"(x));
    return y;
}

__device__ __forceinline__ void gsync(unsigned target) {
    __syncthreads();
    if (threadIdx.x == 0) {
        __threadfence();
        atomicAdd(&g_bar, 1u);
        while (*((volatile unsigned*)&g_bar) < target) __nanosleep(64);
    }
    __syncthreads();
}

__device__ __forceinline__ int edge_at(const void* ei, size_t idx, int is64) {
    if (is64) return (int)((const long long*)ei)[idx];
    return ((const int*)ei)[idx];
}

__device__ __forceinline__ void h8_acc(float* acc, uint4 q) {
    float2 t;
    t = __half22float2(*(__half2*)&q.x); acc[0] += t.x; acc[1] += t.y;
    t = __half22float2(*(__half2*)&q.y); acc[2] += t.x; acc[3] += t.y;
    t = __half22float2(*(__half2*)&q.z); acc[4] += t.x; acc[5] += t.y;
    t = __half22float2(*(__half2*)&q.w); acc[6] += t.x; acc[7] += t.y;
}
__device__ __forceinline__ void h8_unpack(uint4 q, float* f) {
    float2 t;
    t = __half22float2(*(__half2*)&q.x); f[0] = t.x; f[1] = t.y;
    t = __half22float2(*(__half2*)&q.y); f[2] = t.x; f[3] = t.y;
    t = __half22float2(*(__half2*)&q.z); f[4] = t.x; f[5] = t.y;
    t = __half22float2(*(__half2*)&q.w); f[6] = t.x; f[7] = t.y;
}

__device__ __forceinline__ void mma16816(
        float& c0, float& c1, float& c2, float& c3,
        unsigned a0, unsigned a1, unsigned a2, unsigned a3,
        unsigned b0, unsigned b1) {
    asm volatile(
        "mma.sync.aligned.m16n8k16.row.col.f32.f16.f16.f32 "
        "{%0,%1,%2,%3}, {%4,%5,%6,%7}, {%8,%9}, {%0,%1,%2,%3};"
        : "+f"(c0), "+f"(c1), "+f"(c2), "+f"(c3)
        : "r"(a0), "r"(a1), "r"(a2), "r"(a3), "r"(b0), "r"(b1));
}

// ---- tensor GEMM: O16[N,M] = fp16( Xh[N,64] @ W[64,M] )  (no scaling) ------
template <int M>
__device__ void gemm_mma(const __half* __restrict__ Xh, const float* __restrict__ W,
                         __half* __restrict__ O16, int N, SM* sm, int gwarp) {
    __half2* wp = (__half2*)sm->w;
    const int entries = 4 * 2 * M * 4;
    for (int idx = threadIdx.x; idx < entries; idx += TPB) {
        int tg = idx & 3;
        int col = (idx >> 2) % M;
        int rest = (idx >> 2) / M;
        int h = rest & 1, ks = rest >> 1;
        int k0 = ks * 16 + h * 8 + tg * 2;
        wp[idx] = __floats2half2_rn(W[k0 * M + col], W[(k0 + 1) * M + col]);
    }
    __syncthreads();
    int lane = threadIdx.x & 31;
    int g = lane >> 2, tg = lane & 3;
    int tiles = (N + 15) >> 4;
    for (int t = gwarp; t < tiles; t += NWARPS) {
        int rlo = t * 16 + g;
        int rhi = rlo + 8;
        bool oklo = rlo < N, okhi = rhi < N;
        #pragma unroll
        for (int cc = 0; cc < M / 32; cc++) {
            float c[4][4];
            #pragma unroll
            for (int nt = 0; nt < 4; nt++)
                #pragma unroll
                for (int q = 0; q < 4; q++) c[nt][q] = 0.f;
            #pragma unroll
            for (int ks = 0; ks < 4; ks++) {
                unsigned a0 = 0, a1 = 0, a2 = 0, a3 = 0;
                if (oklo) {
                    const __half* p = Xh + (size_t)rlo * 64 + ks * 16 + tg * 2;
                    a0 = *(const unsigned*)p;
                    a2 = *(const unsigned*)(p + 8);
                }
                if (okhi) {
                    const __half* p = Xh + (size_t)rhi * 64 + ks * 16 + tg * 2;
                    a1 = *(const unsigned*)p;
                    a3 = *(const unsigned*)(p + 8);
                }
                #pragma unroll
                for (int nt = 0; nt < 4; nt++) {
                    int col = cc * 32 + nt * 8 + g;
                    unsigned b0 = *(unsigned*)&wp[((ks * 2 + 0) * M + col) * 4 + tg];
                    unsigned b1 = *(unsigned*)&wp[((ks * 2 + 1) * M + col) * 4 + tg];
                    mma16816(c[nt][0], c[nt][1], c[nt][2], c[nt][3],
                             a0, a1, a2, a3, b0, b1);
                }
            }
            #pragma unroll
            for (int nt = 0; nt < 4; nt++) {
                int colst = cc * 32 + nt * 8 + tg * 2;
                if (oklo) {
                    __half2 v = __floats2half2_rn(c[nt][0], c[nt][1]);
                    *(__half2*)(O16 + (size_t)rlo * M + colst) = v;
                }
                if (okhi) {
                    __half2 v = __floats2half2_rn(c[nt][2], c[nt][3]);
                    *(__half2*)(O16 + (size_t)rhi * M + colst) = v;
                }
            }
        }
    }
}

// ---------------------------------------------------------------------------
__global__ void __launch_bounds__(TPB, 5) k_mega(
        const float* __restrict__ x, const void* __restrict__ ei,
        const float* __restrict__ W1, const float* __restrict__ b1,
        const float* __restrict__ W2, const float* __restrict__ b2,
        const float* __restrict__ W3, const float* __restrict__ b3,
        float* __restrict__ out, int N, int E) {
    __shared__ SM sm;
    int gtid = blockIdx.x * TPB + threadIdx.x;
    int lane = threadIdx.x & 31;
    int gwarp = gtid >> 5;

    // warp-parallel dtype detect (first 64 int64 values), per block
    if (threadIdx.x < 32) {
        const long long* p = (const long long*)ei;
        long long v0 = p[threadIdx.x], v1 = p[32 + threadIdx.x];
        int ok = (v0 >= 0 && v0 < (long long)N && v1 >= 0 && v1 < (long long)N);
        unsigned m = __ballot_sync(0xffffffffu, ok);
        if (threadIdx.x == 0) sm.is64 = (m == 0xffffffffu);
    }
    __syncthreads();
    int is64 = sm.is64;

    // Phase A: single-pass CSR fill (counter = degree; overflow list for >32)
    for (int e = gtid; e < E; e += NTH) {
        int s = edge_at(ei, e, is64);
        int d = edge_at(ei, (size_t)E + e, is64);
        int pos = atomicAdd(&g_deg[d], 1);
        if (pos < SLOTS) g_csr32[(size_t)d * SLOTS + pos] = s;
        else {
            int o = atomicAdd(&g_ovfn, 1);
            g_ovf[o] = make_int2(d, s);
        }
    }
    gsync(1u * NB);

    // Phase B: dis + scaled x->fp16 convert + self-pads (8 lanes per node)
    {
        long long items = (long long)N * 8;
        for (long long it = gtid; it < items; it += NTH) {
            int n = (int)(it >> 3);
            int l = (int)(it & 7);
            int d = g_deg[n];
            float dsn = rsqrtf((float)(d + 1));
            if (l == 0) {
                g_dis[n] = dsn;
                int dcap = d < SLOTS ? d : SLOTS;
                int pad = (dcap + 3) & ~3;
                for (int j = dcap; j < pad; j++) g_csr32[(size_t)n * SLOTS + j] = n;
            }
            const float4* xs = (const float4*)(x + (size_t)n * 64 + l * 8);
            float4 u = __ldg(xs), v = __ldg(xs + 1);
            __half2 h0 = __floats2half2_rn(u.x * dsn, u.y * dsn);
            __half2 h1 = __floats2half2_rn(u.z * dsn, u.w * dsn);
            __half2 h2 = __floats2half2_rn(v.x * dsn, v.y * dsn);
            __half2 h3 = __floats2half2_rn(v.z * dsn, v.w * dsn);
            uint4 st;
            st.x = *(unsigned*)&h0; st.y = *(unsigned*)&h1;
            st.z = *(unsigned*)&h2; st.w = *(unsigned*)&h3;
            ((uint4*)g_x16)[(size_t)n * 8 + l] = st;
        }
    }
    gsync(2u * NB);

    // Phase C: GEMM1 (tensor core, x16s @ W1 -> g_h16)
    gemm_mma<64>(g_x16, W1, g_h16, N, &sm, gwarp);
    gsync(3u * NB);

    // Phase D: gather1 (fp16 in, fp32 accum) -> o1s = dis*tanh(...) fp16
    {
        const uint4* __restrict__ Hq = (const uint4*)g_h16;   // 8 uint4 per node
        long long items = (long long)N * 8;
        int ovfn = g_ovfn;
        for (long long it = gtid; it < items; it += NTH) {
            int node = (int)(it >> 3);
            int l = (int)(it & 7);
            int d = g_deg[node];
            int dcap = d < SLOTS ? d : SLOTS;
            int pc = (dcap + 3) >> 2;
            float coef = 1.0f - (float)((pc << 2) - dcap);
            const int4* __restrict__ C4 = (const int4*)(g_csr32 + (size_t)node * SLOTS);
            float acc[8] = {0.f, 0.f, 0.f, 0.f, 0.f, 0.f, 0.f, 0.f};
            for (int j = 0; j < pc; j++) {
                int4 a = __ldg(&C4[j]);
                uint4 q0 = __ldg(&Hq[(size_t)a.x * 8 + l]);
                uint4 q1 = __ldg(&Hq[(size_t)a.y * 8 + l]);
                uint4 q2 = __ldg(&Hq[(size_t)a.z * 8 + l]);
                uint4 q3 = __ldg(&Hq[(size_t)a.w * 8 + l]);
                h8_acc(acc, q0); h8_acc(acc, q1); h8_acc(acc, q2); h8_acc(acc, q3);
            }
            if (d > SLOTS) {                     // rare overflow path
                for (int i = 0; i < ovfn; i++) {
                    int2 p = g_ovf[i];
                    if (p.x == node) {
                        uint4 q = __ldg(&Hq[(size_t)p.y * 8 + l]);
                        h8_acc(acc, q);
                    }
                }
            }
            uint4 qs = __ldg(&Hq[(size_t)node * 8 + l]);
            float s[8]; h8_unpack(qs, s);
            #pragma unroll
            for (int k = 0; k < 8; k++) acc[k] = fmaf(s[k], coef, acc[k]);
            float dsn = g_dis[node];
            float4 ba = __ldg(((const float4*)b1) + 2 * l);
            float4 bb = __ldg(((const float4*)b1) + 2 * l + 1);
            float bv[8] = {ba.x, ba.y, ba.z, ba.w, bb.x, bb.y, bb.z, bb.w};
            float o[8];
            #pragma unroll
            for (int k = 0; k < 8; k++)
                o[k] = dsn * fast_tanh(fmaf(acc[k], dsn, bv[k]));
            __half2 p0 = __floats2half2_rn(o[0], o[1]);
            __half2 p1 = __floats2half2_rn(o[2], o[3]);
            __half2 p2 = __floats2half2_rn(o[4], o[5]);
            __half2 p3 = __floats2half2_rn(o[6], o[7]);
            uint4 st;
            st.x = *(unsigned*)&p0; st.y = *(unsigned*)&p1;
            st.z = *(unsigned*)&p2; st.w = *(unsigned*)&p3;
            ((uint4*)g_o16)[(size_t)node * 8 + l] = st;
        }
    }
    gsync(4u * NB);

    // Phase E: GEMM2 (tensor core, o1s @ W2 -> g_h16, M=32)
    gemm_mma<32>(g_o16, W2, g_h16, N, &sm, gwarp);
    gsync(5u * NB);

    // Phase F: gather2 + tanh + fused projection; 4 lanes/node -> g_s
    {
        const uint4* __restrict__ Hq = (const uint4*)g_h16;   // 4 uint4 per node
        long long items = (long long)N * 4;
        int ovfn = g_ovfn;
        for (long long it = gtid; it < items; it += NTH) {
            int node = (int)(it >> 2);
            int l = (int)(it & 3);
            int d = g_deg[node];
            int dcap = d < SLOTS ? d : SLOTS;
            int pc = (dcap + 3) >> 2;
            float coef = 1.0f - (float)((pc << 2) - dcap);
            const int4* __restrict__ C4 = (const int4*)(g_csr32 + (size_t)node * SLOTS);
            float acc[8] = {0.f, 0.f, 0.f, 0.f, 0.f, 0.f, 0.f, 0.f};
            for (int j = 0; j < pc; j++) {
                int4 a = __ldg(&C4[j]);
                uint4 q0 = __ldg(&Hq[(size_t)a.x * 4 + l]);
                uint4 q1 = __ldg(&Hq[(size_t)a.y * 4 + l]);
                uint4 q2 = __ldg(&Hq[(size_t)a.z * 4 + l]);
                uint4 q3 = __ldg(&Hq[(size_t)a.w * 4 + l]);
                h8_acc(acc, q0); h8_acc(acc, q1); h8_acc(acc, q2); h8_acc(acc, q3);
            }
            if (d > SLOTS) {
                for (int i = 0; i < ovfn; i++) {
                    int2 p = g_ovf[i];
                    if (p.x == node) {
                        uint4 q = __ldg(&Hq[(size_t)p.y * 4 + l]);
                        h8_acc(acc, q);
                    }
                }
            }
            uint4 qs = __ldg(&Hq[(size_t)node * 4 + l]);
            float s[8]; h8_unpack(qs, s);
            #pragma unroll
            for (int k = 0; k < 8; k++) acc[k] = fmaf(s[k], coef, acc[k]);
            float dsn = g_dis[node];
            float4 ba = __ldg(((const float4*)b2) + 2 * l);
            float4 bb = __ldg(((const float4*)b2) + 2 * l + 1);
            float bv[8] = {ba.x, ba.y, ba.z, ba.w, bb.x, bb.y, bb.z, bb.w};
            float4 wa = __ldg(((const float4*)W3) + 2 * l);
            float4 wb = __ldg(((const float4*)W3) + 2 * l + 1);
            float wv[8] = {wa.x, wa.y, wa.z, wa.w, wb.x, wb.y, wb.z, wb.w};
            float partial = 0.f;
            #pragma unroll
            for (int k = 0; k < 8; k++)
                partial += fast_tanh(fmaf(acc[k], dsn, bv[k])) * wv[k];
            partial += __shfl_down_sync(0xffffffffu, partial, 2, 4);
            partial += __shfl_down_sync(0xffffffffu, partial, 1, 4);
            if (l == 0) g_s[node] = dsn * partial;
        }
    }
    gsync(6u * NB);

    // Phase G: scalar gather3; out = dis*(sum + hs3_self) + b3; zero deg
    {
        float bb = __ldg(b3);
        int ovfn = g_ovfn;
        for (int n = gwarp; n < N; n += NWARPS) {
            int d = g_deg[n];
            int c = d < SLOTS ? d : SLOTS;
            const int* __restrict__ C = g_csr32 + (size_t)n * SLOTS;
            float acc = 0.f;
            for (int j = lane; j < c; j += 32)
                acc += __ldg(&g_s[C[j]]);
            if (d > SLOTS) {
                for (int i = lane; i < ovfn; i += 32) {
                    int2 p = g_ovf[i];
                    if (p.x == n) acc += __ldg(&g_s[p.y]);
                }
            }
            #pragma unroll
            for (int off = 16; off; off >>= 1)
                acc += __shfl_down_sync(0xffffffffu, acc, off);
            if (lane == 0) {
                out[n] = fmaf(g_dis[n], acc + g_s[n], bb);
                g_deg[n] = 0;                    // restore invariant
            }
        }
    }

    // final arrival: last CTA resets counters for next graph replay
    __syncthreads();
    if (threadIdx.x == 0) {
        __threadfence();
        unsigned v = atomicAdd(&g_bar, 1u);
        if (v == 7u * NB - 1u) {
            g_bar = 0u; g_ovfn = 0;
        }
    }
}

// ---------------------------------------------------------------------------
extern "C" void kernel_launch(void* const* d_in, const int* in_sizes, int n_in,
                              void* d_out, int out_size) {
    const float* x  = (const float*)d_in[0];
    const void*  ei = d_in[1];
    const float* W1 = (const float*)d_in[2];
    const float* b1 = (const float*)d_in[3];
    const float* W2 = (const float*)d_in[4];
    const float* b2 = (const float*)d_in[5];
    const float* W3 = (const float*)d_in[6];
    const float* b3 = (const float*)d_in[7];
    float* out = (float*)d_out;

    int N = in_sizes[0] / 64;
    int E = in_sizes[1] / 2;

    k_mega<<<NB, TPB>>>(x, ei, W1, b1, W2, b2, W3, b3, out, N, E);
}

// round 15
// speedup vs baseline: 1.8192x; 1.0450x over previous
#include <cuda_runtime.h>
#include <cuda_fp16.h>

// ---------------------------------------------------------------------------
// 3-layer GCN persistent megakernel, round 15 (= round 14 + GEMM1/CSR overlap):
//  - x -> fp16 convert is UNSCALED (no dis dependency), so GEMM1 runs in the
//    same phase as the single-pass CSR fill (row scaling commutes)
//  - h16 rows scaled by dis in the dis/pads phase (replaces x re-read)
//  - fixed-stride CSR (32 slots/node) + overflow list; tensor-core GEMMs
// ---------------------------------------------------------------------------

#define NMAX 100000
#define EMAX 1600000
#define SLOTS 32
#define NB  740          // 148 SMs x 5 CTAs
#define TPB 256
#define NTH (NB * TPB)
#define NWARPS (NTH >> 5)

__device__ unsigned g_bar;        // zero-init; restored to 0 at exit
__device__ int   g_ovfn;          // overflow count; restored at exit
__device__ int   g_deg[NMAX];     // fill counter == degree; zeroed in last phase
__device__ float g_dis[NMAX];
__device__ float g_s[NMAX];       // scalar hs3 per node
__device__ __align__(16) int  g_csr32[(size_t)NMAX * SLOTS];  // fixed-stride CSR
__device__ __align__(16) int2 g_ovf[EMAX];                    // (dst, src) overflow
__device__ __align__(16) __half g_x16[(size_t)NMAX * 64];  // fp16 x (unscaled)
__device__ __align__(16) __half g_h16[(size_t)NMAX * 64];  // fp16 GEMM outputs
__device__ __align__(16) __half g_o16[(size_t)NMAX * 64];  // fp16 dis*o1

struct SM {
    __align__(16) float w[4096];   // aliased as __half2 for B-fragment packs
    int is64;
};

__device__ __forceinline__ float fast_tanh(float x) {
    float y;
    asm("tanh.approx.f32 %0, %1;" : "=f"(y) : "f"(x));
    return y;
}

__device__ __forceinline__ void gsync(unsigned target) {
    __syncthreads();
    if (threadIdx.x == 0) {
        __threadfence();
        atomicAdd(&g_bar, 1u);
        while (*((volatile unsigned*)&g_bar) < target) __nanosleep(64);
    }
    __syncthreads();
}

__device__ __forceinline__ int edge_at(const void* ei, size_t idx, int is64) {
    if (is64) return (int)((const long long*)ei)[idx];
    return ((const int*)ei)[idx];
}

__device__ __forceinline__ void h8_acc(float* acc, uint4 q) {
    float2 t;
    t = __half22float2(*(__half2*)&q.x); acc[0] += t.x; acc[1] += t.y;
    t = __half22float2(*(__half2*)&q.y); acc[2] += t.x; acc[3] += t.y;
    t = __half22float2(*(__half2*)&q.z); acc[4] += t.x; acc[5] += t.y;
    t = __half22float2(*(__half2*)&q.w); acc[6] += t.x; acc[7] += t.y;
}
__device__ __forceinline__ void h8_unpack(uint4 q, float* f) {
    float2 t;
    t = __half22float2(*(__half2*)&q.x); f[0] = t.x; f[1] = t.y;
    t = __half22float2(*(__half2*)&q.y); f[2] = t.x; f[3] = t.y;
    t = __half22float2(*(__half2*)&q.z); f[4] = t.x; f[5] = t.y;
    t = __half22float2(*(__half2*)&q.w); f[6] = t.x; f[7] = t.y;
}

__device__ __forceinline__ void mma16816(
        float& c0, float& c1, float& c2, float& c3,
        unsigned a0, unsigned a1, unsigned a2, unsigned a3,
        unsigned b0, unsigned b1) {
    asm volatile(
        "mma.sync.aligned.m16n8k16.row.col.f32.f16.f16.f32 "
        "{%0,%1,%2,%3}, {%4,%5,%6,%7}, {%8,%9}, {%0,%1,%2,%3};"
        : "+f"(c0), "+f"(c1), "+f"(c2), "+f"(c3)
        : "r"(a0), "r"(a1), "r"(a2), "r"(a3), "r"(b0), "r"(b1));
}

// ---- tensor GEMM: O16[N,M] = fp16( Xh[N,64] @ W[64,M] ) --------------------
template <int M>
__device__ void gemm_mma(const __half* __restrict__ Xh, const float* __restrict__ W,
                         __half* __restrict__ O16, int N, SM* sm, int gwarp) {
    __half2* wp = (__half2*)sm->w;
    const int entries = 4 * 2 * M * 4;
    for (int idx = threadIdx.x; idx < entries; idx += TPB) {
        int tg = idx & 3;
        int col = (idx >> 2) % M;
        int rest = (idx >> 2) / M;
        int h = rest & 1, ks = rest >> 1;
        int k0 = ks * 16 + h * 8 + tg * 2;
        wp[idx] = __floats2half2_rn(W[k0 * M + col], W[(k0 + 1) * M + col]);
    }
    __syncthreads();
    int lane = threadIdx.x & 31;
    int g = lane >> 2, tg = lane & 3;
    int tiles = (N + 15) >> 4;
    for (int t = gwarp; t < tiles; t += NWARPS) {
        int rlo = t * 16 + g;
        int rhi = rlo + 8;
        bool oklo = rlo < N, okhi = rhi < N;
        #pragma unroll
        for (int cc = 0; cc < M / 32; cc++) {
            float c[4][4];
            #pragma unroll
            for (int nt = 0; nt < 4; nt++)
                #pragma unroll
                for (int q = 0; q < 4; q++) c[nt][q] = 0.f;
            #pragma unroll
            for (int ks = 0; ks < 4; ks++) {
                unsigned a0 = 0, a1 = 0, a2 = 0, a3 = 0;
                if (oklo) {
                    const __half* p = Xh + (size_t)rlo * 64 + ks * 16 + tg * 2;
                    a0 = *(const unsigned*)p;
                    a2 = *(const unsigned*)(p + 8);
                }
                if (okhi) {
                    const __half* p = Xh + (size_t)rhi * 64 + ks * 16 + tg * 2;
                    a1 = *(const unsigned*)p;
                    a3 = *(const unsigned*)(p + 8);
                }
                #pragma unroll
                for (int nt = 0; nt < 4; nt++) {
                    int col = cc * 32 + nt * 8 + g;
                    unsigned b0 = *(unsigned*)&wp[((ks * 2 + 0) * M + col) * 4 + tg];
                    unsigned b1 = *(unsigned*)&wp[((ks * 2 + 1) * M + col) * 4 + tg];
                    mma16816(c[nt][0], c[nt][1], c[nt][2], c[nt][3],
                             a0, a1, a2, a3, b0, b1);
                }
            }
            #pragma unroll
            for (int nt = 0; nt < 4; nt++) {
                int colst = cc * 32 + nt * 8 + tg * 2;
                if (oklo) {
                    __half2 v = __floats2half2_rn(c[nt][0], c[nt][1]);
                    *(__half2*)(O16 + (size_t)rlo * M + colst) = v;
                }
                if (okhi) {
                    __half2 v = __floats2half2_rn(c[nt][2], c[nt][3]);
                    *(__half2*)(O16 + (size_t)rhi * M + colst) = v;
                }
            }
        }
    }
}

// ---------------------------------------------------------------------------
__global__ void __launch_bounds__(TPB, 5) k_mega(
        const float* __restrict__ x, const void* __restrict__ ei,
        const float* __restrict__ W1, const float* __restrict__ b1,
        const float* __restrict__ W2, const float* __restrict__ b2,
        const float* __restrict__ W3, const float* __restrict__ b3,
        float* __restrict__ out, int N, int E) {
    __shared__ SM sm;
    int gtid = blockIdx.x * TPB + threadIdx.x;
    int lane = threadIdx.x & 31;
    int gwarp = gtid >> 5;

    // warp-parallel dtype detect (first 64 int64 values), per block
    if (threadIdx.x < 32) {
        const long long* p = (const long long*)ei;
        long long v0 = p[threadIdx.x], v1 = p[32 + threadIdx.x];
        int ok = (v0 >= 0 && v0 < (long long)N && v1 >= 0 && v1 < (long long)N);
        unsigned m = __ballot_sync(0xffffffffu, ok);
        if (threadIdx.x == 0) sm.is64 = (m == 0xffffffffu);
    }
    __syncthreads();
    int is64 = sm.is64;

    // Phase 0: x -> fp16 convert (UNSCALED; no dependencies)
    {
        long long items = (long long)N * 8;
        for (long long i = gtid; i < items; i += NTH) {
            const float4* xs = (const float4*)(x + i * 8);
            float4 u = __ldg(xs), v = __ldg(xs + 1);
            __half2 h0 = __floats2half2_rn(u.x, u.y);
            __half2 h1 = __floats2half2_rn(u.z, u.w);
            __half2 h2 = __floats2half2_rn(v.x, v.y);
            __half2 h3 = __floats2half2_rn(v.z, v.w);
            uint4 st;
            st.x = *(unsigned*)&h0; st.y = *(unsigned*)&h1;
            st.z = *(unsigned*)&h2; st.w = *(unsigned*)&h3;
            ((uint4*)g_x16)[i] = st;
        }
    }
    gsync(1u * NB);

    // Phase 1: GEMM1 (x16 @ W1 -> h16, unscaled) OVERLAPPED with CSR fill
    gemm_mma<64>(g_x16, W1, g_h16, N, &sm, gwarp);
    for (int e = gtid; e < E; e += NTH) {
        int s = edge_at(ei, e, is64);
        int d = edge_at(ei, (size_t)E + e, is64);
        int pos = atomicAdd(&g_deg[d], 1);
        if (pos < SLOTS) g_csr32[(size_t)d * SLOTS + pos] = s;
        else {
            int o = atomicAdd(&g_ovfn, 1);
            g_ovf[o] = make_int2(d, s);
        }
    }
    gsync(2u * NB);

    // Phase 2: dis + scale h16 rows by dis + self-pads (8 lanes per node)
    {
        long long items = (long long)N * 8;
        for (long long it = gtid; it < items; it += NTH) {
            int n = (int)(it >> 3);
            int l = (int)(it & 7);
            int d = g_deg[n];
            float dsn = rsqrtf((float)(d + 1));
            if (l == 0) {
                g_dis[n] = dsn;
                int dcap = d < SLOTS ? d : SLOTS;
                int pad = (dcap + 3) & ~3;
                for (int j = dcap; j < pad; j++) g_csr32[(size_t)n * SLOTS + j] = n;
            }
            uint4 q = ((const uint4*)g_h16)[(size_t)n * 8 + l];
            float f[8]; h8_unpack(q, f);
            __half2 h0 = __floats2half2_rn(f[0] * dsn, f[1] * dsn);
            __half2 h1 = __floats2half2_rn(f[2] * dsn, f[3] * dsn);
            __half2 h2 = __floats2half2_rn(f[4] * dsn, f[5] * dsn);
            __half2 h3 = __floats2half2_rn(f[6] * dsn, f[7] * dsn);
            uint4 st;
            st.x = *(unsigned*)&h0; st.y = *(unsigned*)&h1;
            st.z = *(unsigned*)&h2; st.w = *(unsigned*)&h3;
            ((uint4*)g_h16)[(size_t)n * 8 + l] = st;
        }
    }
    gsync(3u * NB);

    // Phase 3: gather1 (fp16 in, fp32 accum) -> o1s = dis*tanh(...) fp16
    {
        const uint4* __restrict__ Hq = (const uint4*)g_h16;   // 8 uint4 per node
        long long items = (long long)N * 8;
        int ovfn = g_ovfn;
        for (long long it = gtid; it < items; it += NTH) {
            int node = (int)(it >> 3);
            int l = (int)(it & 7);
            int d = g_deg[node];
            int dcap = d < SLOTS ? d : SLOTS;
            int pc = (dcap + 3) >> 2;
            float coef = 1.0f - (float)((pc << 2) - dcap);
            const int4* __restrict__ C4 = (const int4*)(g_csr32 + (size_t)node * SLOTS);
            float acc[8] = {0.f, 0.f, 0.f, 0.f, 0.f, 0.f, 0.f, 0.f};
            for (int j = 0; j < pc; j++) {
                int4 a = __ldg(&C4[j]);
                uint4 q0 = __ldg(&Hq[(size_t)a.x * 8 + l]);
                uint4 q1 = __ldg(&Hq[(size_t)a.y * 8 + l]);
                uint4 q2 = __ldg(&Hq[(size_t)a.z * 8 + l]);
                uint4 q3 = __ldg(&Hq[(size_t)a.w * 8 + l]);
                h8_acc(acc, q0); h8_acc(acc, q1); h8_acc(acc, q2); h8_acc(acc, q3);
            }
            if (d > SLOTS) {                     // rare overflow path
                for (int i = 0; i < ovfn; i++) {
                    int2 p = g_ovf[i];
                    if (p.x == node) {
                        uint4 q = __ldg(&Hq[(size_t)p.y * 8 + l]);
                        h8_acc(acc, q);
                    }
                }
            }
            uint4 qs = __ldg(&Hq[(size_t)node * 8 + l]);
            float s[8]; h8_unpack(qs, s);
            #pragma unroll
            for (int k = 0; k < 8; k++) acc[k] = fmaf(s[k], coef, acc[k]);
            float dsn = g_dis[node];
            float4 ba = __ldg(((const float4*)b1) + 2 * l);
            float4 bb = __ldg(((const float4*)b1) + 2 * l + 1);
            float bv[8] = {ba.x, ba.y, ba.z, ba.w, bb.x, bb.y, bb.z, bb.w};
            float o[8];
            #pragma unroll
            for (int k = 0; k < 8; k++)
                o[k] = dsn * fast_tanh(fmaf(acc[k], dsn, bv[k]));
            __half2 p0 = __floats2half2_rn(o[0], o[1]);
            __half2 p1 = __floats2half2_rn(o[2], o[3]);
            __half2 p2 = __floats2half2_rn(o[4], o[5]);
            __half2 p3 = __floats2half2_rn(o[6], o[7]);
            uint4 st;
            st.x = *(unsigned*)&p0; st.y = *(unsigned*)&p1;
            st.z = *(unsigned*)&p2; st.w = *(unsigned*)&p3;
            ((uint4*)g_o16)[(size_t)node * 8 + l] = st;
        }
    }
    gsync(4u * NB);

    // Phase 4: GEMM2 (tensor core, o1s @ W2 -> g_h16, M=32)
    gemm_mma<32>(g_o16, W2, g_h16, N, &sm, gwarp);
    gsync(5u * NB);

    // Phase 5: gather2 + tanh + fused projection; 4 lanes/node -> g_s
    {
        const uint4* __restrict__ Hq = (const uint4*)g_h16;   // 4 uint4 per node
        long long items = (long long)N * 4;
        int ovfn = g_ovfn;
        for (long long it = gtid; it < items; it += NTH) {
            int node = (int)(it >> 2);
            int l = (int)(it & 3);
            int d = g_deg[node];
            int dcap = d < SLOTS ? d : SLOTS;
            int pc = (dcap + 3) >> 2;
            float coef = 1.0f - (float)((pc << 2) - dcap);
            const int4* __restrict__ C4 = (const int4*)(g_csr32 + (size_t)node * SLOTS);
            float acc[8] = {0.f, 0.f, 0.f, 0.f, 0.f, 0.f, 0.f, 0.f};
            for (int j = 0; j < pc; j++) {
                int4 a = __ldg(&C4[j]);
                uint4 q0 = __ldg(&Hq[(size_t)a.x * 4 + l]);
                uint4 q1 = __ldg(&Hq[(size_t)a.y * 4 + l]);
                uint4 q2 = __ldg(&Hq[(size_t)a.z * 4 + l]);
                uint4 q3 = __ldg(&Hq[(size_t)a.w * 4 + l]);
                h8_acc(acc, q0); h8_acc(acc, q1); h8_acc(acc, q2); h8_acc(acc, q3);
            }
            if (d > SLOTS) {
                for (int i = 0; i < ovfn; i++) {
                    int2 p = g_ovf[i];
                    if (p.x == node) {
                        uint4 q = __ldg(&Hq[(size_t)p.y * 4 + l]);
                        h8_acc(acc, q);
                    }
                }
            }
            uint4 qs = __ldg(&Hq[(size_t)node * 4 + l]);
            float s[8]; h8_unpack(qs, s);
            #pragma unroll
            for (int k = 0; k < 8; k++) acc[k] = fmaf(s[k], coef, acc[k]);
            float dsn = g_dis[node];
            float4 ba = __ldg(((const float4*)b2) + 2 * l);
            float4 bb = __ldg(((const float4*)b2) + 2 * l + 1);
            float bv[8] = {ba.x, ba.y, ba.z, ba.w, bb.x, bb.y, bb.z, bb.w};
            float4 wa = __ldg(((const float4*)W3) + 2 * l);
            float4 wb = __ldg(((const float4*)W3) + 2 * l + 1);
            float wv[8] = {wa.x, wa.y, wa.z, wa.w, wb.x, wb.y, wb.z, wb.w};
            float partial = 0.f;
            #pragma unroll
            for (int k = 0; k < 8; k++)
                partial += fast_tanh(fmaf(acc[k], dsn, bv[k])) * wv[k];
            partial += __shfl_down_sync(0xffffffffu, partial, 2, 4);
            partial += __shfl_down_sync(0xffffffffu, partial, 1, 4);
            if (l == 0) g_s[node] = dsn * partial;
        }
    }
    gsync(6u * NB);

    // Phase 6: scalar gather3; out = dis*(sum + hs3_self) + b3; zero deg
    {
        float bb = __ldg(b3);
        int ovfn = g_ovfn;
        for (int n = gwarp; n < N; n += NWARPS) {
            int d = g_deg[n];
            int c = d < SLOTS ? d : SLOTS;
            const int* __restrict__ C = g_csr32 + (size_t)n * SLOTS;
            float acc = 0.f;
            for (int j = lane; j < c; j += 32)
                acc += __ldg(&g_s[C[j]]);
            if (d > SLOTS) {
                for (int i = lane; i < ovfn; i += 32) {
                    int2 p = g_ovf[i];
                    if (p.x == n) acc += __ldg(&g_s[p.y]);
                }
            }
            #pragma unroll
            for (int off = 16; off; off >>= 1)
                acc += __shfl_down_sync(0xffffffffu, acc, off);
            if (lane == 0) {
                out[n] = fmaf(g_dis[n], acc + g_s[n], bb);
                g_deg[n] = 0;                    // restore invariant
            }
        }
    }

    // final arrival: last CTA resets counters for next graph replay
    __syncthreads();
    if (threadIdx.x == 0) {
        __threadfence();
        unsigned v = atomicAdd(&g_bar, 1u);
        if (v == 7u * NB - 1u) {
            g_bar = 0u; g_ovfn = 0;
        }
    }
}

// ---------------------------------------------------------------------------
extern "C" void kernel_launch(void* const* d_in, const int* in_sizes, int n_in,
                              void* d_out, int out_size) {
    const float* x  = (const float*)d_in[0];
    const void*  ei = d_in[1];
    const float* W1 = (const float*)d_in[2];
    const float* b1 = (const float*)d_in[3];
    const float* W2 = (const float*)d_in[4];
    const float* b2 = (const float*)d_in[5];
    const float* W3 = (const float*)d_in[6];
    const float* b3 = (const float*)d_in[7];
    float* out = (float*)d_out;

    int N = in_sizes[0] / 64;
    int E = in_sizes[1] / 2;

    k_mega<<<NB, TPB>>>(x, ei, W1, b1, W2, b2, W3, b3, out, N, E);
}

// round 16
// speedup vs baseline: 1.9055x; 1.0474x over previous
#include <cuda_runtime.h>
#include <cuda_fp16.h>

// ---------------------------------------------------------------------------
// 3-layer GCN persistent megakernel, round 16:
//  - edge pass runs alone (deg final); GEMM1 reads fp32 x directly, converts
//    A-fragments in registers, applies dis-scale in epilogue -> h16 stored
//    scaled ONCE (deletes the x-convert pass and the h-rescale pass)
//  - 6 phases / 6 barriers; fixed-stride CSR (32 slots) + overflow list
//  - tensor-core GEMMs (m16n8k16 fp16/fp32), round-9 gather shape
// ---------------------------------------------------------------------------

#define NMAX 100000
#define EMAX 1600000
#define SLOTS 32
#define NB  740          // 148 SMs x 5 CTAs
#define TPB 256
#define NTH (NB * TPB)
#define NWARPS (NTH >> 5)

__device__ unsigned g_bar;        // zero-init; restored to 0 at exit
__device__ int   g_ovfn;          // overflow count; restored at exit
__device__ int   g_deg[NMAX];     // fill counter == degree; zeroed in last phase
__device__ float g_dis[NMAX];
__device__ float g_s[NMAX];       // scalar hs3 per node
__device__ __align__(16) int  g_csr32[(size_t)NMAX * SLOTS];  // fixed-stride CSR
__device__ __align__(16) int2 g_ovf[EMAX];                    // (dst, src) overflow
__device__ __align__(16) __half g_h16[(size_t)NMAX * 64];  // fp16 GEMM outputs (scaled)
__device__ __align__(16) __half g_o16[(size_t)NMAX * 64];  // fp16 dis*o1

struct SM {
    __align__(16) float w[4096];   // aliased as __half2 for B-fragment packs
    int is64;
};

__device__ __forceinline__ float fast_tanh(float x) {
    float y;
    asm("tanh.approx.f32 %0, %1;" : "=f"(y) : "f"(x));
    return y;
}

__device__ __forceinline__ void gsync(unsigned target) {
    __syncthreads();
    if (threadIdx.x == 0) {
        __threadfence();
        atomicAdd(&g_bar, 1u);
        while (*((volatile unsigned*)&g_bar) < target) __nanosleep(64);
    }
    __syncthreads();
}

__device__ __forceinline__ int edge_at(const void* ei, size_t idx, int is64) {
    if (is64) return (int)((const long long*)ei)[idx];
    return ((const int*)ei)[idx];
}

__device__ __forceinline__ void h8_acc(float* acc, uint4 q) {
    float2 t;
    t = __half22float2(*(__half2*)&q.x); acc[0] += t.x; acc[1] += t.y;
    t = __half22float2(*(__half2*)&q.y); acc[2] += t.x; acc[3] += t.y;
    t = __half22float2(*(__half2*)&q.z); acc[4] += t.x; acc[5] += t.y;
    t = __half22float2(*(__half2*)&q.w); acc[6] += t.x; acc[7] += t.y;
}
__device__ __forceinline__ void h8_unpack(uint4 q, float* f) {
    float2 t;
    t = __half22float2(*(__half2*)&q.x); f[0] = t.x; f[1] = t.y;
    t = __half22float2(*(__half2*)&q.y); f[2] = t.x; f[3] = t.y;
    t = __half22float2(*(__half2*)&q.z); f[4] = t.x; f[5] = t.y;
    t = __half22float2(*(__half2*)&q.w); f[6] = t.x; f[7] = t.y;
}

__device__ __forceinline__ void mma16816(
        float& c0, float& c1, float& c2, float& c3,
        unsigned a0, unsigned a1, unsigned a2, unsigned a3,
        unsigned b0, unsigned b1) {
    asm volatile(
        "mma.sync.aligned.m16n8k16.row.col.f32.f16.f16.f32 "
        "{%0,%1,%2,%3}, {%4,%5,%6,%7}, {%8,%9}, {%0,%1,%2,%3};"
        : "+f"(c0), "+f"(c1), "+f"(c2), "+f"(c3)
        : "r"(a0), "r"(a1), "r"(a2), "r"(a3), "r"(b0), "r"(b1));
}

// pack W[64,M] into B-fragment layout in smem
template <int M>
__device__ __forceinline__ void pack_w(const float* __restrict__ W, SM* sm) {
    __half2* wp = (__half2*)sm->w;
    const int entries = 4 * 2 * M * 4;
    for (int idx = threadIdx.x; idx < entries; idx += TPB) {
        int tg = idx & 3;
        int col = (idx >> 2) % M;
        int rest = (idx >> 2) / M;
        int h = rest & 1, ks = rest >> 1;
        int k0 = ks * 16 + h * 8 + tg * 2;
        wp[idx] = __floats2half2_rn(W[k0 * M + col], W[(k0 + 1) * M + col]);
    }
    __syncthreads();
}

// ---- GEMM1: H16[N,64] = fp16( dis[row] * (fp32 X[N,64] @ W1[64,64]) ) ------
// A fragments converted fp32->fp16 in registers; dis from g_deg in epilogue.
__device__ void gemm1_mma(const float* __restrict__ X, __half* __restrict__ O16,
                          int N, SM* sm, int gwarp) {
    constexpr int M = 64;
    __half2* wp = (__half2*)sm->w;
    int lane = threadIdx.x & 31;
    int g = lane >> 2, tg = lane & 3;
    int tiles = (N + 15) >> 4;
    for (int t = gwarp; t < tiles; t += NWARPS) {
        int rlo = t * 16 + g;
        int rhi = rlo + 8;
        bool oklo = rlo < N, okhi = rhi < N;
        float dlo = oklo ? rsqrtf((float)(g_deg[rlo] + 1)) : 0.f;
        float dhi = okhi ? rsqrtf((float)(g_deg[rhi] + 1)) : 0.f;
        #pragma unroll
        for (int cc = 0; cc < M / 32; cc++) {
            float c[4][4];
            #pragma unroll
            for (int nt = 0; nt < 4; nt++)
                #pragma unroll
                for (int q = 0; q < 4; q++) c[nt][q] = 0.f;
            #pragma unroll
            for (int ks = 0; ks < 4; ks++) {
                unsigned a0 = 0, a1 = 0, a2 = 0, a3 = 0;
                if (oklo) {
                    const float* p = X + (size_t)rlo * 64 + ks * 16 + tg * 2;
                    float2 u = *(const float2*)p;
                    float2 v = *(const float2*)(p + 8);
                    __half2 ha = __floats2half2_rn(u.x, u.y);
                    __half2 hb = __floats2half2_rn(v.x, v.y);
                    a0 = *(unsigned*)&ha; a2 = *(unsigned*)&hb;
                }
                if (okhi) {
                    const float* p = X + (size_t)rhi * 64 + ks * 16 + tg * 2;
                    float2 u = *(const float2*)p;
                    float2 v = *(const float2*)(p + 8);
                    __half2 ha = __floats2half2_rn(u.x, u.y);
                    __half2 hb = __floats2half2_rn(v.x, v.y);
                    a1 = *(unsigned*)&ha; a3 = *(unsigned*)&hb;
                }
                #pragma unroll
                for (int nt = 0; nt < 4; nt++) {
                    int col = cc * 32 + nt * 8 + g;
                    unsigned b0 = *(unsigned*)&wp[((ks * 2 + 0) * M + col) * 4 + tg];
                    unsigned b1 = *(unsigned*)&wp[((ks * 2 + 1) * M + col) * 4 + tg];
                    mma16816(c[nt][0], c[nt][1], c[nt][2], c[nt][3],
                             a0, a1, a2, a3, b0, b1);
                }
            }
            #pragma unroll
            for (int nt = 0; nt < 4; nt++) {
                int colst = cc * 32 + nt * 8 + tg * 2;
                if (oklo) {
                    __half2 v = __floats2half2_rn(c[nt][0] * dlo, c[nt][1] * dlo);
                    *(__half2*)(O16 + (size_t)rlo * M + colst) = v;
                }
                if (okhi) {
                    __half2 v = __floats2half2_rn(c[nt][2] * dhi, c[nt][3] * dhi);
                    *(__half2*)(O16 + (size_t)rhi * M + colst) = v;
                }
            }
        }
    }
}

// ---- GEMM2: O16[N,32] = fp16( Xh[N,64] @ W2[64,32] )  (input pre-scaled) ---
__device__ void gemm2_mma(const __half* __restrict__ Xh, __half* __restrict__ O16,
                          int N, SM* sm, int gwarp) {
    constexpr int M = 32;
    __half2* wp = (__half2*)sm->w;
    int lane = threadIdx.x & 31;
    int g = lane >> 2, tg = lane & 3;
    int tiles = (N + 15) >> 4;
    for (int t = gwarp; t < tiles; t += NWARPS) {
        int rlo = t * 16 + g;
        int rhi = rlo + 8;
        bool oklo = rlo < N, okhi = rhi < N;
        float c[4][4];
        #pragma unroll
        for (int nt = 0; nt < 4; nt++)
            #pragma unroll
            for (int q = 0; q < 4; q++) c[nt][q] = 0.f;
        #pragma unroll
        for (int ks = 0; ks < 4; ks++) {
            unsigned a0 = 0, a1 = 0, a2 = 0, a3 = 0;
            if (oklo) {
                const __half* p = Xh + (size_t)rlo * 64 + ks * 16 + tg * 2;
                a0 = *(const unsigned*)p;
                a2 = *(const unsigned*)(p + 8);
            }
            if (okhi) {
                const __half* p = Xh + (size_t)rhi * 64 + ks * 16 + tg * 2;
                a1 = *(const unsigned*)p;
                a3 = *(const unsigned*)(p + 8);
            }
            #pragma unroll
            for (int nt = 0; nt < 4; nt++) {
                int col = nt * 8 + g;
                unsigned b0 = *(unsigned*)&wp[((ks * 2 + 0) * M + col) * 4 + tg];
                unsigned b1 = *(unsigned*)&wp[((ks * 2 + 1) * M + col) * 4 + tg];
                mma16816(c[nt][0], c[nt][1], c[nt][2], c[nt][3],
                         a0, a1, a2, a3, b0, b1);
            }
        }
        #pragma unroll
        for (int nt = 0; nt < 4; nt++) {
            int colst = nt * 8 + tg * 2;
            if (oklo) {
                __half2 v = __floats2half2_rn(c[nt][0], c[nt][1]);
                *(__half2*)(O16 + (size_t)rlo * M + colst) = v;
            }
            if (okhi) {
                __half2 v = __floats2half2_rn(c[nt][2], c[nt][3]);
                *(__half2*)(O16 + (size_t)rhi * M + colst) = v;
            }
        }
    }
}

// ---------------------------------------------------------------------------
__global__ void __launch_bounds__(TPB, 5) k_mega(
        const float* __restrict__ x, const void* __restrict__ ei,
        const float* __restrict__ W1, const float* __restrict__ b1,
        const float* __restrict__ W2, const float* __restrict__ b2,
        const float* __restrict__ W3, const float* __restrict__ b3,
        float* __restrict__ out, int N, int E) {
    __shared__ SM sm;
    int gtid = blockIdx.x * TPB + threadIdx.x;
    int lane = threadIdx.x & 31;
    int gwarp = gtid >> 5;

    // warp-parallel dtype detect (first 64 int64 values), per block
    if (threadIdx.x < 32) {
        const long long* p = (const long long*)ei;
        long long v0 = p[threadIdx.x], v1 = p[32 + threadIdx.x];
        int ok = (v0 >= 0 && v0 < (long long)N && v1 >= 0 && v1 < (long long)N);
        unsigned m = __ballot_sync(0xffffffffu, ok);
        if (threadIdx.x == 0) sm.is64 = (m == 0xffffffffu);
    }
    __syncthreads();
    int is64 = sm.is64;

    // Phase 0: single-pass CSR fill (counter = degree; overflow for >32)
    for (int e = gtid; e < E; e += NTH) {
        int s = edge_at(ei, e, is64);
        int d = edge_at(ei, (size_t)E + e, is64);
        int pos = atomicAdd(&g_deg[d], 1);
        if (pos < SLOTS) g_csr32[(size_t)d * SLOTS + pos] = s;
        else {
            int o = atomicAdd(&g_ovfn, 1);
            g_ovf[o] = make_int2(d, s);
        }
    }
    gsync(1u * NB);

    // Phase 1: GEMM1 (fp32 x, inline convert, dis-scale epilogue) + dis/pads
    pack_w<64>(W1, &sm);
    gemm1_mma(x, g_h16, N, &sm, gwarp);
    for (int n = gtid; n < N; n += NTH) {
        int d = g_deg[n];
        g_dis[n] = rsqrtf((float)(d + 1));
        int dcap = d < SLOTS ? d : SLOTS;
        int pad = (dcap + 3) & ~3;
        for (int j = dcap; j < pad; j++) g_csr32[(size_t)n * SLOTS + j] = n;
    }
    gsync(2u * NB);

    // Phase 2: gather1 (fp16 in, fp32 accum) -> o1s = dis*tanh(...) fp16
    {
        const uint4* __restrict__ Hq = (const uint4*)g_h16;   // 8 uint4 per node
        long long items = (long long)N * 8;
        int ovfn = g_ovfn;
        for (long long it = gtid; it < items; it += NTH) {
            int node = (int)(it >> 3);
            int l = (int)(it & 7);
            int d = g_deg[node];
            int dcap = d < SLOTS ? d : SLOTS;
            int pc = (dcap + 3) >> 2;
            float coef = 1.0f - (float)((pc << 2) - dcap);
            const int4* __restrict__ C4 = (const int4*)(g_csr32 + (size_t)node * SLOTS);
            float acc[8] = {0.f, 0.f, 0.f, 0.f, 0.f, 0.f, 0.f, 0.f};
            for (int j = 0; j < pc; j++) {
                int4 a = __ldg(&C4[j]);
                uint4 q0 = __ldg(&Hq[(size_t)a.x * 8 + l]);
                uint4 q1 = __ldg(&Hq[(size_t)a.y * 8 + l]);
                uint4 q2 = __ldg(&Hq[(size_t)a.z * 8 + l]);
                uint4 q3 = __ldg(&Hq[(size_t)a.w * 8 + l]);
                h8_acc(acc, q0); h8_acc(acc, q1); h8_acc(acc, q2); h8_acc(acc, q3);
            }
            if (d > SLOTS) {                     // rare overflow path
                for (int i = 0; i < ovfn; i++) {
                    int2 p = g_ovf[i];
                    if (p.x == node) {
                        uint4 q = __ldg(&Hq[(size_t)p.y * 8 + l]);
                        h8_acc(acc, q);
                    }
                }
            }
            uint4 qs = __ldg(&Hq[(size_t)node * 8 + l]);
            float s[8]; h8_unpack(qs, s);
            #pragma unroll
            for (int k = 0; k < 8; k++) acc[k] = fmaf(s[k], coef, acc[k]);
            float dsn = g_dis[node];
            float4 ba = __ldg(((const float4*)b1) + 2 * l);
            float4 bb = __ldg(((const float4*)b1) + 2 * l + 1);
            float bv[8] = {ba.x, ba.y, ba.z, ba.w, bb.x, bb.y, bb.z, bb.w};
            float o[8];
            #pragma unroll
            for (int k = 0; k < 8; k++)
                o[k] = dsn * fast_tanh(fmaf(acc[k], dsn, bv[k]));
            __half2 p0 = __floats2half2_rn(o[0], o[1]);
            __half2 p1 = __floats2half2_rn(o[2], o[3]);
            __half2 p2 = __floats2half2_rn(o[4], o[5]);
            __half2 p3 = __floats2half2_rn(o[6], o[7]);
            uint4 st;
            st.x = *(unsigned*)&p0; st.y = *(unsigned*)&p1;
            st.z = *(unsigned*)&p2; st.w = *(unsigned*)&p3;
            ((uint4*)g_o16)[(size_t)node * 8 + l] = st;
        }
    }
    gsync(3u * NB);

    // Phase 3: GEMM2 (tensor core, o1s @ W2 -> g_h16, M=32)
    pack_w<32>(W2, &sm);
    gemm2_mma(g_o16, g_h16, N, &sm, gwarp);
    gsync(4u * NB);

    // Phase 4: gather2 + tanh + fused projection; 4 lanes/node -> g_s
    {
        const uint4* __restrict__ Hq = (const uint4*)g_h16;   // 4 uint4 per node
        long long items = (long long)N * 4;
        int ovfn = g_ovfn;
        for (long long it = gtid; it < items; it += NTH) {
            int node = (int)(it >> 2);
            int l = (int)(it & 3);
            int d = g_deg[node];
            int dcap = d < SLOTS ? d : SLOTS;
            int pc = (dcap + 3) >> 2;
            float coef = 1.0f - (float)((pc << 2) - dcap);
            const int4* __restrict__ C4 = (const int4*)(g_csr32 + (size_t)node * SLOTS);
            float acc[8] = {0.f, 0.f, 0.f, 0.f, 0.f, 0.f, 0.f, 0.f};
            for (int j = 0; j < pc; j++) {
                int4 a = __ldg(&C4[j]);
                uint4 q0 = __ldg(&Hq[(size_t)a.x * 4 + l]);
                uint4 q1 = __ldg(&Hq[(size_t)a.y * 4 + l]);
                uint4 q2 = __ldg(&Hq[(size_t)a.z * 4 + l]);
                uint4 q3 = __ldg(&Hq[(size_t)a.w * 4 + l]);
                h8_acc(acc, q0); h8_acc(acc, q1); h8_acc(acc, q2); h8_acc(acc, q3);
            }
            if (d > SLOTS) {
                for (int i = 0; i < ovfn; i++) {
                    int2 p = g_ovf[i];
                    if (p.x == node) {
                        uint4 q = __ldg(&Hq[(size_t)p.y * 4 + l]);
                        h8_acc(acc, q);
                    }
                }
            }
            uint4 qs = __ldg(&Hq[(size_t)node * 4 + l]);
            float s[8]; h8_unpack(qs, s);
            #pragma unroll
            for (int k = 0; k < 8; k++) acc[k] = fmaf(s[k], coef, acc[k]);
            float dsn = g_dis[node];
            float4 ba = __ldg(((const float4*)b2) + 2 * l);
            float4 bb = __ldg(((const float4*)b2) + 2 * l + 1);
            float bv[8] = {ba.x, ba.y, ba.z, ba.w, bb.x, bb.y, bb.z, bb.w};
            float4 wa = __ldg(((const float4*)W3) + 2 * l);
            float4 wb = __ldg(((const float4*)W3) + 2 * l + 1);
            float wv[8] = {wa.x, wa.y, wa.z, wa.w, wb.x, wb.y, wb.z, wb.w};
            float partial = 0.f;
            #pragma unroll
            for (int k = 0; k < 8; k++)
                partial += fast_tanh(fmaf(acc[k], dsn, bv[k])) * wv[k];
            partial += __shfl_down_sync(0xffffffffu, partial, 2, 4);
            partial += __shfl_down_sync(0xffffffffu, partial, 1, 4);
            if (l == 0) g_s[node] = dsn * partial;
        }
    }
    gsync(5u * NB);

    // Phase 5: scalar gather3; out = dis*(sum + hs3_self) + b3; zero deg
    {
        float bb = __ldg(b3);
        int ovfn = g_ovfn;
        for (int n = gwarp; n < N; n += NWARPS) {
            int d = g_deg[n];
            int c = d < SLOTS ? d : SLOTS;
            const int* __restrict__ C = g_csr32 + (size_t)n * SLOTS;
            float acc = 0.f;
            for (int j = lane; j < c; j += 32)
                acc += __ldg(&g_s[C[j]]);
            if (d > SLOTS) {
                for (int i = lane; i < ovfn; i += 32) {
                    int2 p = g_ovf[i];
                    if (p.x == n) acc += __ldg(&g_s[p.y]);
                }
            }
            #pragma unroll
            for (int off = 16; off; off >>= 1)
                acc += __shfl_down_sync(0xffffffffu, acc, off);
            if (lane == 0) {
                out[n] = fmaf(g_dis[n], acc + g_s[n], bb);
                g_deg[n] = 0;                    // restore invariant
            }
        }
    }

    // final arrival: last CTA resets counters for next graph replay
    __syncthreads();
    if (threadIdx.x == 0) {
        __threadfence();
        unsigned v = atomicAdd(&g_bar, 1u);
        if (v == 6u * NB - 1u) {
            g_bar = 0u; g_ovfn = 0;
        }
    }
}

// ---------------------------------------------------------------------------
extern "C" void kernel_launch(void* const* d_in, const int* in_sizes, int n_in,
                              void* d_out, int out_size) {
    const float* x  = (const float*)d_in[0];
    const void*  ei = d_in[1];
    const float* W1 = (const float*)d_in[2];
    const float* b1 = (const float*)d_in[3];
    const float* W2 = (const float*)d_in[4];
    const float* b2 = (const float*)d_in[5];
    const float* W3 = (const float*)d_in[6];
    const float* b3 = (const float*)d_in[7];
    float* out = (float*)d_out;

    int N = in_sizes[0] / 64;
    int E = in_sizes[1] / 2;

    k_mega<<<NB, TPB>>>(x, ei, W1, b1, W2, b2, W3, b3, out, N, E);
}

// round 17
// speedup vs baseline: 1.9767x; 1.0374x over previous
#include <cuda_runtime.h>
#include <cuda_fp16.h>

// ---------------------------------------------------------------------------
// 3-layer GCN persistent megakernel, round 17 (= round 16 + edge-pass MLP +
// weight-pack hoisting):
//  - edge pass: 2 edges/thread via 16B index loads, unroll x4 (8 atomic
//    chains in flight); scalar fallback for odd E
//  - pack_w<64> hidden under the edge pass; pack_w<32> under gather1
//  - otherwise identical to round 16 (bit-identical numerics)
// ---------------------------------------------------------------------------

#define NMAX 100000
#define EMAX 1600000
#define SLOTS 32
#define NB  740          // 148 SMs x 5 CTAs
#define TPB 256
#define NTH (NB * TPB)
#define NWARPS (NTH >> 5)

__device__ unsigned g_bar;        // zero-init; restored to 0 at exit
__device__ int   g_ovfn;          // overflow count; restored at exit
__device__ int   g_deg[NMAX];     // fill counter == degree; zeroed in last phase
__device__ float g_dis[NMAX];
__device__ float g_s[NMAX];       // scalar hs3 per node
__device__ __align__(16) int  g_csr32[(size_t)NMAX * SLOTS];  // fixed-stride CSR
__device__ __align__(16) int2 g_ovf[EMAX];                    // (dst, src) overflow
__device__ __align__(16) __half g_h16[(size_t)NMAX * 64];  // fp16 GEMM outputs (scaled)
__device__ __align__(16) __half g_o16[(size_t)NMAX * 64];  // fp16 dis*o1

struct SM {
    __align__(16) float w[4096];   // aliased as __half2 for B-fragment packs
    int is64;
};

__device__ __forceinline__ float fast_tanh(float x) {
    float y;
    asm("tanh.approx.f32 %0, %1;" : "=f"(y) : "f"(x));
    return y;
}

__device__ __forceinline__ void gsync(unsigned target) {
    __syncthreads();
    if (threadIdx.x == 0) {
        __threadfence();
        atomicAdd(&g_bar, 1u);
        while (*((volatile unsigned*)&g_bar) < target) __nanosleep(64);
    }
    __syncthreads();
}

__device__ __forceinline__ int edge_at(const void* ei, size_t idx, int is64) {
    if (is64) return (int)((const long long*)ei)[idx];
    return ((const int*)ei)[idx];
}

__device__ __forceinline__ void csr_insert(int d, int s) {
    int pos = atomicAdd(&g_deg[d], 1);
    if (pos < SLOTS) g_csr32[(size_t)d * SLOTS + pos] = s;
    else {
        int o = atomicAdd(&g_ovfn, 1);
        g_ovf[o] = make_int2(d, s);
    }
}

__device__ __forceinline__ void h8_acc(float* acc, uint4 q) {
    float2 t;
    t = __half22float2(*(__half2*)&q.x); acc[0] += t.x; acc[1] += t.y;
    t = __half22float2(*(__half2*)&q.y); acc[2] += t.x; acc[3] += t.y;
    t = __half22float2(*(__half2*)&q.z); acc[4] += t.x; acc[5] += t.y;
    t = __half22float2(*(__half2*)&q.w); acc[6] += t.x; acc[7] += t.y;
}
__device__ __forceinline__ void h8_unpack(uint4 q, float* f) {
    float2 t;
    t = __half22float2(*(__half2*)&q.x); f[0] = t.x; f[1] = t.y;
    t = __half22float2(*(__half2*)&q.y); f[2] = t.x; f[3] = t.y;
    t = __half22float2(*(__half2*)&q.z); f[4] = t.x; f[5] = t.y;
    t = __half22float2(*(__half2*)&q.w); f[6] = t.x; f[7] = t.y;
}

__device__ __forceinline__ void mma16816(
        float& c0, float& c1, float& c2, float& c3,
        unsigned a0, unsigned a1, unsigned a2, unsigned a3,
        unsigned b0, unsigned b1) {
    asm volatile(
        "mma.sync.aligned.m16n8k16.row.col.f32.f16.f16.f32 "
        "{%0,%1,%2,%3}, {%4,%5,%6,%7}, {%8,%9}, {%0,%1,%2,%3};"
        : "+f"(c0), "+f"(c1), "+f"(c2), "+f"(c3)
        : "r"(a0), "r"(a1), "r"(a2), "r"(a3), "r"(b0), "r"(b1));
}

// pack W[64,M] into B-fragment layout in smem (ends with __syncthreads)
template <int M>
__device__ __forceinline__ void pack_w(const float* __restrict__ W, SM* sm) {
    __half2* wp = (__half2*)sm->w;
    const int entries = 4 * 2 * M * 4;
    for (int idx = threadIdx.x; idx < entries; idx += TPB) {
        int tg = idx & 3;
        int col = (idx >> 2) % M;
        int rest = (idx >> 2) / M;
        int h = rest & 1, ks = rest >> 1;
        int k0 = ks * 16 + h * 8 + tg * 2;
        wp[idx] = __floats2half2_rn(W[k0 * M + col], W[(k0 + 1) * M + col]);
    }
    __syncthreads();
}

// ---- GEMM1: H16[N,64] = fp16( dis[row] * (fp32 X[N,64] @ W1[64,64]) ) ------
__device__ void gemm1_mma(const float* __restrict__ X, __half* __restrict__ O16,
                          int N, SM* sm, int gwarp) {
    constexpr int M = 64;
    __half2* wp = (__half2*)sm->w;
    int lane = threadIdx.x & 31;
    int g = lane >> 2, tg = lane & 3;
    int tiles = (N + 15) >> 4;
    for (int t = gwarp; t < tiles; t += NWARPS) {
        int rlo = t * 16 + g;
        int rhi = rlo + 8;
        bool oklo = rlo < N, okhi = rhi < N;
        float dlo = oklo ? rsqrtf((float)(g_deg[rlo] + 1)) : 0.f;
        float dhi = okhi ? rsqrtf((float)(g_deg[rhi] + 1)) : 0.f;
        #pragma unroll
        for (int cc = 0; cc < M / 32; cc++) {
            float c[4][4];
            #pragma unroll
            for (int nt = 0; nt < 4; nt++)
                #pragma unroll
                for (int q = 0; q < 4; q++) c[nt][q] = 0.f;
            #pragma unroll
            for (int ks = 0; ks < 4; ks++) {
                unsigned a0 = 0, a1 = 0, a2 = 0, a3 = 0;
                if (oklo) {
                    const float* p = X + (size_t)rlo * 64 + ks * 16 + tg * 2;
                    float2 u = *(const float2*)p;
                    float2 v = *(const float2*)(p + 8);
                    __half2 ha = __floats2half2_rn(u.x, u.y);
                    __half2 hb = __floats2half2_rn(v.x, v.y);
                    a0 = *(unsigned*)&ha; a2 = *(unsigned*)&hb;
                }
                if (okhi) {
                    const float* p = X + (size_t)rhi * 64 + ks * 16 + tg * 2;
                    float2 u = *(const float2*)p;
                    float2 v = *(const float2*)(p + 8);
                    __half2 ha = __floats2half2_rn(u.x, u.y);
                    __half2 hb = __floats2half2_rn(v.x, v.y);
                    a1 = *(unsigned*)&ha; a3 = *(unsigned*)&hb;
                }
                #pragma unroll
                for (int nt = 0; nt < 4; nt++) {
                    int col = cc * 32 + nt * 8 + g;
                    unsigned b0 = *(unsigned*)&wp[((ks * 2 + 0) * M + col) * 4 + tg];
                    unsigned b1 = *(unsigned*)&wp[((ks * 2 + 1) * M + col) * 4 + tg];
                    mma16816(c[nt][0], c[nt][1], c[nt][2], c[nt][3],
                             a0, a1, a2, a3, b0, b1);
                }
            }
            #pragma unroll
            for (int nt = 0; nt < 4; nt++) {
                int colst = cc * 32 + nt * 8 + tg * 2;
                if (oklo) {
                    __half2 v = __floats2half2_rn(c[nt][0] * dlo, c[nt][1] * dlo);
                    *(__half2*)(O16 + (size_t)rlo * M + colst) = v;
                }
                if (okhi) {
                    __half2 v = __floats2half2_rn(c[nt][2] * dhi, c[nt][3] * dhi);
                    *(__half2*)(O16 + (size_t)rhi * M + colst) = v;
                }
            }
        }
    }
}

// ---- GEMM2: O16[N,32] = fp16( Xh[N,64] @ W2[64,32] )  (input pre-scaled) ---
__device__ void gemm2_mma(const __half* __restrict__ Xh, __half* __restrict__ O16,
                          int N, SM* sm, int gwarp) {
    constexpr int M = 32;
    __half2* wp = (__half2*)sm->w;
    int lane = threadIdx.x & 31;
    int g = lane >> 2, tg = lane & 3;
    int tiles = (N + 15) >> 4;
    for (int t = gwarp; t < tiles; t += NWARPS) {
        int rlo = t * 16 + g;
        int rhi = rlo + 8;
        bool oklo = rlo < N, okhi = rhi < N;
        float c[4][4];
        #pragma unroll
        for (int nt = 0; nt < 4; nt++)
            #pragma unroll
            for (int q = 0; q < 4; q++) c[nt][q] = 0.f;
        #pragma unroll
        for (int ks = 0; ks < 4; ks++) {
            unsigned a0 = 0, a1 = 0, a2 = 0, a3 = 0;
            if (oklo) {
                const __half* p = Xh + (size_t)rlo * 64 + ks * 16 + tg * 2;
                a0 = *(const unsigned*)p;
                a2 = *(const unsigned*)(p + 8);
            }
            if (okhi) {
                const __half* p = Xh + (size_t)rhi * 64 + ks * 16 + tg * 2;
                a1 = *(const unsigned*)p;
                a3 = *(const unsigned*)(p + 8);
            }
            #pragma unroll
            for (int nt = 0; nt < 4; nt++) {
                int col = nt * 8 + g;
                unsigned b0 = *(unsigned*)&wp[((ks * 2 + 0) * M + col) * 4 + tg];
                unsigned b1 = *(unsigned*)&wp[((ks * 2 + 1) * M + col) * 4 + tg];
                mma16816(c[nt][0], c[nt][1], c[nt][2], c[nt][3],
                         a0, a1, a2, a3, b0, b1);
            }
        }
        #pragma unroll
        for (int nt = 0; nt < 4; nt++) {
            int colst = nt * 8 + tg * 2;
            if (oklo) {
                __half2 v = __floats2half2_rn(c[nt][0], c[nt][1]);
                *(__half2*)(O16 + (size_t)rlo * M + colst) = v;
            }
            if (okhi) {
                __half2 v = __floats2half2_rn(c[nt][2], c[nt][3]);
                *(__half2*)(O16 + (size_t)rhi * M + colst) = v;
            }
        }
    }
}

// ---------------------------------------------------------------------------
__global__ void __launch_bounds__(TPB, 5) k_mega(
        const float* __restrict__ x, const void* __restrict__ ei,
        const float* __restrict__ W1, const float* __restrict__ b1,
        const float* __restrict__ W2, const float* __restrict__ b2,
        const float* __restrict__ W3, const float* __restrict__ b3,
        float* __restrict__ out, int N, int E) {
    __shared__ SM sm;
    int gtid = blockIdx.x * TPB + threadIdx.x;
    int lane = threadIdx.x & 31;
    int gwarp = gtid >> 5;

    // warp-parallel dtype detect (first 64 int64 values), per block
    if (threadIdx.x < 32) {
        const long long* p = (const long long*)ei;
        long long v0 = p[threadIdx.x], v1 = p[32 + threadIdx.x];
        int ok = (v0 >= 0 && v0 < (long long)N && v1 >= 0 && v1 < (long long)N);
        unsigned m = __ballot_sync(0xffffffffu, ok);
        if (threadIdx.x == 0) sm.is64 = (m == 0xffffffffu);
    }
    __syncthreads();
    int is64 = sm.is64;

    // Phase 0: pack W1 (hidden) + single-pass CSR fill, 2 edges/thread, MLP x8
    pack_w<64>(W1, &sm);
    if ((E & 1) == 0) {
        int npairs = E >> 1;
        if (is64) {
            const longlong2* sp = (const longlong2*)ei;
            const longlong2* dp = (const longlong2*)((const long long*)ei + E);
            #pragma unroll 4
            for (int p = gtid; p < npairs; p += NTH) {
                longlong2 sv = __ldg(&sp[p]);
                longlong2 dv = __ldg(&dp[p]);
                csr_insert((int)dv.x, (int)sv.x);
                csr_insert((int)dv.y, (int)sv.y);
            }
        } else {
            const int2* sp = (const int2*)ei;
            const int2* dp = (const int2*)((const int*)ei + E);
            #pragma unroll 4
            for (int p = gtid; p < npairs; p += NTH) {
                int2 sv = __ldg(&sp[p]);
                int2 dv = __ldg(&dp[p]);
                csr_insert(dv.x, sv.x);
                csr_insert(dv.y, sv.y);
            }
        }
    } else {
        for (int e = gtid; e < E; e += NTH) {
            int s = edge_at(ei, e, is64);
            int d = edge_at(ei, (size_t)E + e, is64);
            csr_insert(d, s);
        }
    }
    gsync(1u * NB);

    // Phase 1: GEMM1 (fp32 x, inline convert, dis-scale epilogue) + dis/pads
    gemm1_mma(x, g_h16, N, &sm, gwarp);
    for (int n = gtid; n < N; n += NTH) {
        int d = g_deg[n];
        g_dis[n] = rsqrtf((float)(d + 1));
        int dcap = d < SLOTS ? d : SLOTS;
        int pad = (dcap + 3) & ~3;
        for (int j = dcap; j < pad; j++) g_csr32[(size_t)n * SLOTS + j] = n;
    }
    gsync(2u * NB);

    // Phase 2: gather1 -> o1s = dis*tanh(...) fp16; then pack W2 (hidden)
    {
        const uint4* __restrict__ Hq = (const uint4*)g_h16;   // 8 uint4 per node
        long long items = (long long)N * 8;
        int ovfn = g_ovfn;
        for (long long it = gtid; it < items; it += NTH) {
            int node = (int)(it >> 3);
            int l = (int)(it & 7);
            int d = g_deg[node];
            int dcap = d < SLOTS ? d : SLOTS;
            int pc = (dcap + 3) >> 2;
            float coef = 1.0f - (float)((pc << 2) - dcap);
            const int4* __restrict__ C4 = (const int4*)(g_csr32 + (size_t)node * SLOTS);
            float acc[8] = {0.f, 0.f, 0.f, 0.f, 0.f, 0.f, 0.f, 0.f};
            for (int j = 0; j < pc; j++) {
                int4 a = __ldg(&C4[j]);
                uint4 q0 = __ldg(&Hq[(size_t)a.x * 8 + l]);
                uint4 q1 = __ldg(&Hq[(size_t)a.y * 8 + l]);
                uint4 q2 = __ldg(&Hq[(size_t)a.z * 8 + l]);
                uint4 q3 = __ldg(&Hq[(size_t)a.w * 8 + l]);
                h8_acc(acc, q0); h8_acc(acc, q1); h8_acc(acc, q2); h8_acc(acc, q3);
            }
            if (d > SLOTS) {                     // rare overflow path
                for (int i = 0; i < ovfn; i++) {
                    int2 p = g_ovf[i];
                    if (p.x == node) {
                        uint4 q = __ldg(&Hq[(size_t)p.y * 8 + l]);
                        h8_acc(acc, q);
                    }
                }
            }
            uint4 qs = __ldg(&Hq[(size_t)node * 8 + l]);
            float s[8]; h8_unpack(qs, s);
            #pragma unroll
            for (int k = 0; k < 8; k++) acc[k] = fmaf(s[k], coef, acc[k]);
            float dsn = g_dis[node];
            float4 ba = __ldg(((const float4*)b1) + 2 * l);
            float4 bb = __ldg(((const float4*)b1) + 2 * l + 1);
            float bv[8] = {ba.x, ba.y, ba.z, ba.w, bb.x, bb.y, bb.z, bb.w};
            float o[8];
            #pragma unroll
            for (int k = 0; k < 8; k++)
                o[k] = dsn * fast_tanh(fmaf(acc[k], dsn, bv[k]));
            __half2 p0 = __floats2half2_rn(o[0], o[1]);
            __half2 p1 = __floats2half2_rn(o[2], o[3]);
            __half2 p2 = __floats2half2_rn(o[4], o[5]);
            __half2 p3 = __floats2half2_rn(o[6], o[7]);
            uint4 st;
            st.x = *(unsigned*)&p0; st.y = *(unsigned*)&p1;
            st.z = *(unsigned*)&p2; st.w = *(unsigned*)&p3;
            ((uint4*)g_o16)[(size_t)node * 8 + l] = st;
        }
    }
    pack_w<32>(W2, &sm);     // hidden here; GEMM2 starts right after barrier
    gsync(3u * NB);

    // Phase 3: GEMM2 (tensor core, o1s @ W2 -> g_h16, M=32)
    gemm2_mma(g_o16, g_h16, N, &sm, gwarp);
    gsync(4u * NB);

    // Phase 4: gather2 + tanh + fused projection; 4 lanes/node -> g_s
    {
        const uint4* __restrict__ Hq = (const uint4*)g_h16;   // 4 uint4 per node
        long long items = (long long)N * 4;
        int ovfn = g_ovfn;
        for (long long it = gtid; it < items; it += NTH) {
            int node = (int)(it >> 2);
            int l = (int)(it & 3);
            int d = g_deg[node];
            int dcap = d < SLOTS ? d : SLOTS;
            int pc = (dcap + 3) >> 2;
            float coef = 1.0f - (float)((pc << 2) - dcap);
            const int4* __restrict__ C4 = (const int4*)(g_csr32 + (size_t)node * SLOTS);
            float acc[8] = {0.f, 0.f, 0.f, 0.f, 0.f, 0.f, 0.f, 0.f};
            for (int j = 0; j < pc; j++) {
                int4 a = __ldg(&C4[j]);
                uint4 q0 = __ldg(&Hq[(size_t)a.x * 4 + l]);
                uint4 q1 = __ldg(&Hq[(size_t)a.y * 4 + l]);
                uint4 q2 = __ldg(&Hq[(size_t)a.z * 4 + l]);
                uint4 q3 = __ldg(&Hq[(size_t)a.w * 4 + l]);
                h8_acc(acc, q0); h8_acc(acc, q1); h8_acc(acc, q2); h8_acc(acc, q3);
            }
            if (d > SLOTS) {
                for (int i = 0; i < ovfn; i++) {
                    int2 p = g_ovf[i];
                    if (p.x == node) {
                        uint4 q = __ldg(&Hq[(size_t)p.y * 4 + l]);
                        h8_acc(acc, q);
                    }
                }
            }
            uint4 qs = __ldg(&Hq[(size_t)node * 4 + l]);
            float s[8]; h8_unpack(qs, s);
            #pragma unroll
            for (int k = 0; k < 8; k++) acc[k] = fmaf(s[k], coef, acc[k]);
            float dsn = g_dis[node];
            float4 ba = __ldg(((const float4*)b2) + 2 * l);
            float4 bb = __ldg(((const float4*)b2) + 2 * l + 1);
            float bv[8] = {ba.x, ba.y, ba.z, ba.w, bb.x, bb.y, bb.z, bb.w};
            float4 wa = __ldg(((const float4*)W3) + 2 * l);
            float4 wb = __ldg(((const float4*)W3) + 2 * l + 1);
            float wv[8] = {wa.x, wa.y, wa.z, wa.w, wb.x, wb.y, wb.z, wb.w};
            float partial = 0.f;
            #pragma unroll
            for (int k = 0; k < 8; k++)
                partial += fast_tanh(fmaf(acc[k], dsn, bv[k])) * wv[k];
            partial += __shfl_down_sync(0xffffffffu, partial, 2, 4);
            partial += __shfl_down_sync(0xffffffffu, partial, 1, 4);
            if (l == 0) g_s[node] = dsn * partial;
        }
    }
    gsync(5u * NB);

    // Phase 5: scalar gather3; out = dis*(sum + hs3_self) + b3; zero deg
    {
        float bb = __ldg(b3);
        int ovfn = g_ovfn;
        for (int n = gwarp; n < N; n += NWARPS) {
            int d = g_deg[n];
            int c = d < SLOTS ? d : SLOTS;
            const int* __restrict__ C = g_csr32 + (size_t)n * SLOTS;
            float acc = 0.f;
            for (int j = lane; j < c; j += 32)
                acc += __ldg(&g_s[C[j]]);
            if (d > SLOTS) {
                for (int i = lane; i < ovfn; i += 32) {
                    int2 p = g_ovf[i];
                    if (p.x == n) acc += __ldg(&g_s[p.y]);
                }
            }
            #pragma unroll
            for (int off = 16; off; off >>= 1)
                acc += __shfl_down_sync(0xffffffffu, acc, off);
            if (lane == 0) {
                out[n] = fmaf(g_dis[n], acc + g_s[n], bb);
                g_deg[n] = 0;                    // restore invariant
            }
        }
    }

    // final arrival: last CTA resets counters for next graph replay
    __syncthreads();
    if (threadIdx.x == 0) {
        __threadfence();
        unsigned v = atomicAdd(&g_bar, 1u);
        if (v == 6u * NB - 1u) {
            g_bar = 0u; g_ovfn = 0;
        }
    }
}

// ---------------------------------------------------------------------------
extern "C" void kernel_launch(void* const* d_in, const int* in_sizes, int n_in,
                              void* d_out, int out_size) {
    const float* x  = (const float*)d_in[0];
    const void*  ei = d_in[1];
    const float* W1 = (const float*)d_in[2];
    const float* b1 = (const float*)d_in[3];
    const float* W2 = (const float*)d_in[4];
    const float* b2 = (const float*)d_in[5];
    const float* W3 = (const float*)d_in[6];
    const float* b3 = (const float*)d_in[7];
    float* out = (float*)d_out;

    int N = in_sizes[0] / 64;
    int E = in_sizes[1] / 2;

    k_mega<<<NB, TPB>>>(x, ei, W1, b1, W2, b2, W3, b3, out, N, E);
}